// round 1
// baseline (speedup 1.0000x reference)
#include <cuda_runtime.h>
#include <cuda_bf16.h>
#include <math.h>

// ---------------- problem constants ----------------
constexpr int Bv   = 8;      // videos
constexpr int Cc   = 256;    // feature dim
constexpr int Nn   = 128;    // N
constexpr int NNe  = Nn*Nn;  // 16384
constexpr int Sv   = 32;     // sentences
constexpr int Mv   = 64;     // moments
constexpr int Pn   = 8256;   // N*(N+1)/2 proposals
constexpr int BP   = Bv*Pn;  // 66048
constexpr int RT   = 128;    // pos rows = M*K
constexpr int NBLK = BP/64;  // 1032 GEMM column tiles (64 | P: 8256 = 64*129)

// T=0.1, margin=0, neg_iou=0.5, K=2, s_per=4, m_per=2, mK=4, E=512

// ---------------- scratch (__device__ globals; no allocs allowed) ----------------
__device__ __align__(16) int            g_flat[Pn];            // p -> i*N+j
__device__ __align__(16) float          g_inv[BP];             // 1/||vf||
__device__ __align__(16) __nv_bfloat16  g_vfb[(size_t)BP*Cc];  // normalized bf16 feats (33.8MB)
__device__ __align__(16) unsigned char  g_iou[Sv*Pn];          // iou2d_p > 0.5
__device__ __align__(16) int            g_topk[Mv*2];
__device__ __align__(16) __nv_bfloat16  g_posb[RT*Cc];         // pos feats bf16
__device__ __align__(16) float          g_posf[RT*Cc];         // pos feats fp32
__device__ __align__(16) float          g_partial[NBLK*RT];    // per-tile masked exp sums
__device__ __align__(16) float          g_negsum[RT];
__device__ __align__(16) float          g_ploss[Sv];

// ---------------- fast exp2 (FMA pipe, avoids MUFU bottleneck) ----------------
__device__ __forceinline__ float fexp2(float x) {
    // x in ~[-14.6, 14.6]; round-to-nearest-int via float bit trick
    float z = __fadd_rn(x, 12582912.0f);                 // 1.5*2^23
    float f = __fsub_rn(x, __fsub_rn(z, 12582912.0f));   // frac in [-0.5, 0.5]
    int   e = __float_as_int(z) << 23;                   // n << 23 (exponent bump)
    float p = 1.3333558146e-3f;
    p = __fmaf_rn(p, f, 9.6181291918e-3f);
    p = __fmaf_rn(p, f, 5.5504108664e-2f);
    p = __fmaf_rn(p, f, 2.4022650696e-1f);
    p = __fmaf_rn(p, f, 6.9314718056e-1f);
    p = __fmaf_rn(p, f, 1.0f);
    return __int_as_float(__float_as_int(p) + e);
}

// ---------------- K0: upper-tri flat index table ----------------
__global__ void k_flat() {
    int idx = blockIdx.x*256 + threadIdx.x;
    if (idx < NNe) {
        int i = idx >> 7, j = idx & 127;
        if (j >= i) {
            int p = i*Nn - (i*(i-1))/2 + (j - i);
            g_flat[p] = idx;
        }
    }
}

// ---------------- K1: gather + L2 norm + bf16 emit ----------------
// grid (P/32, B), 256 threads. Tile: 32 proposals x 256 channels.
__global__ __launch_bounds__(256) void k_norm(const float* __restrict__ vf) {
    __shared__ float tile[32*257];
    __shared__ float ssb[8][32];
    __shared__ float sinv[32];
    int b = blockIdx.y, p0 = blockIdx.x*32, t = threadIdx.x;
    int p = t & 31, c0 = t >> 5;   // warp = one c-slab, lanes = 32 consecutive proposals
    int fi = g_flat[p0 + p];
    const float* base = vf + (size_t)b*Cc*NNe + fi;
    float ss = 0.f;
    #pragma unroll
    for (int k = 0; k < 32; k++) {
        int c = c0*32 + k;
        float v = base[(size_t)c*NNe];
        tile[p*257 + c] = v;
        ss += v*v;
    }
    ssb[c0][p] = ss;
    __syncthreads();
    if (t < 32) {
        float tot = 0.f;
        #pragma unroll
        for (int k = 0; k < 8; k++) tot += ssb[k][t];
        float inv = 1.0f / fmaxf(sqrtf(tot), 1e-12f);
        sinv[t] = inv;
        g_inv[b*Pn + p0 + t] = inv;
    }
    __syncthreads();
    int rowbase = b*Pn + p0;
    #pragma unroll
    for (int it = 0; it < 16; it++) {
        int id = it*256 + t;
        int pr = id >> 7, c2 = (id & 127)*2;
        float inv = sinv[pr];
        __nv_bfloat162 h = __floats2bfloat162_rn(tile[pr*257+c2]*inv, tile[pr*257+c2+1]*inv);
        *reinterpret_cast<__nv_bfloat162*>(g_vfb + (size_t)(rowbase+pr)*Cc + c2) = h;
    }
}

// ---------------- K2: iou2d mask bits ----------------
__global__ void k_iou(const float* __restrict__ iou2d) {
    int p = blockIdx.x*256 + threadIdx.x;
    int s = blockIdx.y;
    if (p < Pn)
        g_iou[s*Pn + p] = (iou2d[(size_t)s*NNe + g_flat[p]] > 0.5f) ? 1 : 0;
}

// ---------------- K3: top-2 per moment (jax.lax.top_k semantics) ----------------
__global__ void k_topk(const float* __restrict__ iou2ds) {
    __shared__ float sv[256];
    __shared__ int   si[256];
    int m = blockIdx.x, t = threadIdx.x;
    const float* row = iou2ds + (size_t)m*NNe;

    float bv = -1e30f; int bi = 0x7fffffff;
    for (int p = t; p < Pn; p += 256) {
        float v = row[g_flat[p]];
        if (v > bv || (v == bv && p < bi)) { bv = v; bi = p; }
    }
    sv[t] = bv; si[t] = bi; __syncthreads();
    for (int off = 128; off > 0; off >>= 1) {
        if (t < off) {
            float v2 = sv[t+off]; int i2 = si[t+off];
            if (v2 > sv[t] || (v2 == sv[t] && i2 < si[t])) { sv[t] = v2; si[t] = i2; }
        }
        __syncthreads();
    }
    int i1 = si[0];
    __syncthreads();

    bv = -1e30f; bi = 0x7fffffff;
    for (int p = t; p < Pn; p += 256) {
        if (p == i1) continue;
        float v = row[g_flat[p]];
        if (v > bv || (v == bv && p < bi)) { bv = v; bi = p; }
    }
    sv[t] = bv; si[t] = bi; __syncthreads();
    for (int off = 128; off > 0; off >>= 1) {
        if (t < off) {
            float v2 = sv[t+off]; int i2 = si[t+off];
            if (v2 > sv[t] || (v2 == sv[t] && i2 < si[t])) { sv[t] = v2; si[t] = i2; }
        }
        __syncthreads();
    }
    if (t == 0) { g_topk[m*2] = i1; g_topk[m*2+1] = si[0]; }
}

// ---------------- K4: build pos feature rows (bf16 for GEMM, fp32 for pairs) ----------------
__global__ void k_pos(const float* __restrict__ vf) {
    int r = blockIdx.x;         // 0..127
    int c = threadIdx.x;        // 0..255
    int m = r >> 1, k = r & 1;
    int j = g_topk[m*2 + k];
    int b = m >> 3;             // scatter_m2v
    int row = b*Pn + j;
    g_posb[r*Cc + c] = g_vfb[(size_t)row*Cc + c];
    g_posf[r*Cc + c] = vf[((size_t)b*Cc + c)*NNe + g_flat[j]] * g_inv[row];
}

// ---------------- K5: fused bf16 GEMM + masked exp row-sum ----------------
__device__ __forceinline__ void ldm4(unsigned addr, unsigned &r0, unsigned &r1, unsigned &r2, unsigned &r3) {
    asm volatile("ldmatrix.sync.aligned.m8n8.x4.shared.b16 {%0,%1,%2,%3}, [%4];"
                 : "=r"(r0), "=r"(r1), "=r"(r2), "=r"(r3) : "r"(addr));
}
__device__ __forceinline__ void mma16816(float* c, unsigned a0, unsigned a1, unsigned a2, unsigned a3,
                                         unsigned b0, unsigned b1) {
    asm volatile("mma.sync.aligned.m16n8k16.row.col.f32.bf16.bf16.f32 "
                 "{%0,%1,%2,%3}, {%4,%5,%6,%7}, {%8,%9}, {%0,%1,%2,%3};"
                 : "+f"(c[0]), "+f"(c[1]), "+f"(c[2]), "+f"(c[3])
                 : "r"(a0), "r"(a1), "r"(a2), "r"(a3), "r"(b0), "r"(b1));
}

constexpr int GEMM_SMEM = 128*512 + 64*512 + 32*64;  // A + B + iou bits = 100352 B

__global__ __launch_bounds__(256) void k_gemm() {
    extern __shared__ unsigned char smem[];
    __nv_bfloat16* sA = reinterpret_cast<__nv_bfloat16*>(smem);
    __nv_bfloat16* sB = reinterpret_cast<__nv_bfloat16*>(smem + 128*512);
    unsigned char* sI = smem + 128*512 + 64*512;

    int t = threadIdx.x;
    int gp0 = blockIdx.x * 64;
    int b   = gp0 / Pn;         // tile never straddles a video (64 | P)
    int j0  = gp0 - b*Pn;

    // iou mask bits for this 64-col tile, all 32 sentences
    for (int i = t; i < 32*64; i += 256) {
        int s = i >> 6, n = i & 63;
        sI[i] = g_iou[s*Pn + j0 + n];
    }
    // load A (128x256 bf16) with XOR-8 16B-chunk swizzle
    {
        const float4* gA = reinterpret_cast<const float4*>(g_posb);
        float4* s4 = reinterpret_cast<float4*>(sA);
        #pragma unroll
        for (int i = t; i < 128*32; i += 256) {
            int row = i >> 5, ch = i & 31;
            s4[row*32 + (ch ^ (row & 7))] = gA[row*32 + ch];
        }
    }
    // load B (64x256 bf16)
    {
        const float4* gB = reinterpret_cast<const float4*>(g_vfb + (size_t)(b*Pn + j0)*Cc);
        float4* s4 = reinterpret_cast<float4*>(sB);
        #pragma unroll
        for (int i = t; i < 64*32; i += 256) {
            int row = i >> 5, ch = i & 31;
            s4[row*32 + (ch ^ (row & 7))] = gB[row*32 + ch];
        }
    }
    __syncthreads();

    int w = t >> 5, l = t & 31;
    int m0 = w * 16;                       // warp's 16 pos rows

    float acc[8][4];
    #pragma unroll
    for (int i = 0; i < 8; i++)
        #pragma unroll
        for (int q = 0; q < 4; q++) acc[i][q] = 0.f;

    unsigned sa = (unsigned)__cvta_generic_to_shared(sA);
    unsigned sb = (unsigned)__cvta_generic_to_shared(sB);

    int rowA     = m0 + (l & 7) + ((l >> 3) & 1) * 8;
    int chSelA   = (l >> 4);
    int rowBbase = (l & 7) + ((l >> 4) & 1) * 8;
    int chSelB   = (l >> 3) & 1;

    #pragma unroll
    for (int ks = 0; ks < 16; ks++) {
        unsigned a0, a1, a2, a3;
        int chA = 2*ks + chSelA;
        ldm4(sa + rowA*512 + (((chA ^ (rowA & 7)) & 31) << 4), a0, a1, a2, a3);
        #pragma unroll
        for (int ntp = 0; ntp < 4; ntp++) {
            int rowB = ntp*16 + rowBbase;
            int chB  = 2*ks + chSelB;
            unsigned b0, b1, b2, b3;
            ldm4(sb + rowB*512 + (((chB ^ (rowB & 7)) & 31) << 4), b0, b1, b2, b3);
            mma16816(acc[ntp*2],     a0, a1, a2, a3, b0, b1);
            mma16816(acc[ntp*2 + 1], a0, a1, a2, a3, b2, b3);
        }
    }

    // epilogue: exp(dot/T) with neg mask, per-row sums
    const float K2E = 14.4269504088896340f;   // log2(e)/T
    int mr = l >> 2;
    int nb = (l & 3) * 2;
    int rLo = m0 + mr, rHi = rLo + 8;
    int sLo = rLo >> 2, sHi = rHi >> 2;
    bool own = (w == b);                       // warp w == video w's rows
    float sumLo = 0.f, sumHi = 0.f;
    #pragma unroll
    for (int nt = 0; nt < 8; nt++) {
        #pragma unroll
        for (int q = 0; q < 2; q++) {
            int n = nt*8 + nb + q;
            float eLo = fexp2(acc[nt][q]   * K2E);
            float eHi = fexp2(acc[nt][2+q] * K2E);
            bool mLo = own && sI[sLo*64 + n];
            bool mHi = own && sI[sHi*64 + n];
            sumLo += mLo ? 0.f : eLo;
            sumHi += mHi ? 0.f : eHi;
        }
    }
    sumLo += __shfl_xor_sync(0xffffffffu, sumLo, 1);
    sumLo += __shfl_xor_sync(0xffffffffu, sumLo, 2);
    sumHi += __shfl_xor_sync(0xffffffffu, sumHi, 1);
    sumHi += __shfl_xor_sync(0xffffffffu, sumHi, 2);
    if ((l & 3) == 0) {
        g_partial[blockIdx.x*RT + rLo] = sumLo;
        g_partial[blockIdx.x*RT + rHi] = sumHi;
    }
}

// ---------------- K6a: deterministic reduce of per-tile partials ----------------
__global__ void k_negred() {
    int r = threadIdx.x;   // 128 threads
    float s0 = 0, s1 = 0, s2 = 0, s3 = 0;
    for (int pb = 0; pb < NBLK; pb += 4) {
        s0 += g_partial[(pb+0)*RT + r];
        s1 += g_partial[(pb+1)*RT + r];
        s2 += g_partial[(pb+2)*RT + r];
        s3 += g_partial[(pb+3)*RT + r];
    }
    g_negsum[r] = (s0 + s1) + (s2 + s3);
}

// ---------------- K6b: per-sentence pair terms (fp32 dots) ----------------
__global__ void k_pairs() {
    __shared__ float sp[4*256];
    __shared__ float terms[16];
    int s = blockIdx.x, t = threadIdx.x;   // 128 threads
    for (int i = t; i < 1024; i += 128) sp[i] = g_posf[s*4*256 + i];
    __syncthreads();
    int pair = t >> 3, cc = t & 7;
    int a_ref = pair >> 2, a_pos = pair & 3;
    float d = 0.f;
    #pragma unroll
    for (int k = 0; k < 32; k++) {
        int c = cc*32 + k;
        d += sp[a_ref*256 + c] * sp[a_pos*256 + c];
    }
    d += __shfl_xor_sync(0xffffffffu, d, 1);
    d += __shfl_xor_sync(0xffffffffu, d, 2);
    d += __shfl_xor_sync(0xffffffffu, d, 4);
    if (cc == 0) {
        float x = d * 10.0f;                      // (ps - margin)/T
        float ns = g_negsum[s*4 + a_ref];
        terms[pair] = -(x - logf(expf(x) + ns));
    }
    __syncthreads();
    if (t == 0) {
        float su = 0.f;
        #pragma unroll
        for (int i = 0; i < 16; i++) su += terms[i];
        g_ploss[s] = su;
    }
}

// ---------------- K6c: final mean ----------------
__global__ void k_final(float* out) {
    if (threadIdx.x == 0) {
        float su = 0.f;
        #pragma unroll
        for (int i = 0; i < Sv; i++) su += g_ploss[i];
        out[0] = su * (1.0f / 512.0f);   // mean over E, WEIGHT = 1
    }
}

// ---------------- launch ----------------
extern "C" void kernel_launch(void* const* d_in, const int* in_sizes, int n_in,
                              void* d_out, int out_size) {
    const float* video  = (const float*)d_in[0];
    // d_in[1] sents_feats, d_in[2] num_sentences, d_in[3] num_targets: unused
    const float* iou2d  = (const float*)d_in[4];
    const float* iou2ds = (const float*)d_in[5];
    float* out = (float*)d_out;

    cudaFuncSetAttribute(k_gemm, cudaFuncAttributeMaxDynamicSharedMemorySize, GEMM_SMEM);

    k_flat<<<64, 256>>>();
    k_norm<<<dim3(Pn/32, Bv), 256>>>(video);
    k_iou<<<dim3(33, Sv), 256>>>(iou2d);
    k_topk<<<Mv, 256>>>(iou2ds);
    k_pos<<<RT, 256>>>(video);
    k_gemm<<<NBLK, 256, GEMM_SMEM>>>();
    k_negred<<<1, 128>>>();
    k_pairs<<<Sv, 128>>>();
    k_final<<<1, 32>>>(out);
}

// round 7
// speedup vs baseline: 1.0787x; 1.0787x over previous
#include <cuda_runtime.h>
#include <cuda_bf16.h>
#include <math.h>

// ---------------- problem constants ----------------
constexpr int Bv   = 8;      // videos
constexpr int Cc   = 256;    // feature dim
constexpr int Nn   = 128;    // N
constexpr int NNe  = Nn*Nn;  // 16384
constexpr int Sv   = 32;     // sentences
constexpr int Mv   = 64;     // moments
constexpr int Pn   = 8256;   // N*(N+1)/2 proposals
constexpr int BP   = Bv*Pn;  // 66048
constexpr int RT   = 128;    // pos rows = M*K
constexpr int NBLK = BP/64;  // 1032 GEMM column tiles (64 | P)
constexpr int CHUNK = Pn/8;  // 1032 topk chunk

// ---------------- scratch ----------------
__device__ __align__(16) int            g_flat[Pn];
__device__ __align__(16) float          g_inv[BP];
__device__ __align__(16) __nv_bfloat16  g_vfb[(size_t)BP*Cc];
__device__ __align__(16) unsigned char  g_iou[Sv*Pn];
__device__ __align__(16) float          g_cv[Mv*16];
__device__ __align__(16) int            g_ci[Mv*16];
__device__ __align__(16) __nv_bfloat16  g_posb[RT*Cc];
__device__ __align__(16) float          g_posf[RT*Cc];
__device__ __align__(16) float          g_partial[NBLK*RT];
__device__ __align__(16) float          g_negsum[RT];
__device__ __align__(16) float          g_ploss[Sv];

// ---------------- fast exp2 on FMA pipe ----------------
__device__ __forceinline__ float fexp2(float x) {
    float z = __fadd_rn(x, 12582912.0f);
    float f = __fsub_rn(x, __fsub_rn(z, 12582912.0f));
    int   e = __float_as_int(z) << 23;
    float p = 1.3333558146e-3f;
    p = __fmaf_rn(p, f, 9.6181291918e-3f);
    p = __fmaf_rn(p, f, 5.5504108664e-2f);
    p = __fmaf_rn(p, f, 2.4022650696e-1f);
    p = __fmaf_rn(p, f, 6.9314718056e-1f);
    p = __fmaf_rn(p, f, 1.0f);
    return __int_as_float(__float_as_int(p) + e);
}

// ---------------- K0: upper-tri flat index table ----------------
__global__ void k_flat() {
    int idx = blockIdx.x*256 + threadIdx.x;
    if (idx < NNe) {
        int i = idx >> 7, j = idx & 127;
        if (j >= i) g_flat[i*Nn - (i*(i-1))/2 + (j - i)] = idx;
    }
}

// ---------------- K1: gather + L2 norm + bf16 emit ----------------
__global__ __launch_bounds__(256) void k_norm(const float* __restrict__ vf) {
    __shared__ float tile[32*257];
    __shared__ float ssb[8][32];
    __shared__ float sinv[32];
    int b = blockIdx.y, p0 = blockIdx.x*32, t = threadIdx.x;
    int p = t & 31, c0 = t >> 5;
    int fi = g_flat[p0 + p];
    const float* base = vf + (size_t)b*Cc*NNe + fi;
    float ss = 0.f;
    #pragma unroll
    for (int k = 0; k < 32; k++) {
        int c = c0*32 + k;
        float v = base[(size_t)c*NNe];
        tile[p*257 + c] = v;
        ss += v*v;
    }
    ssb[c0][p] = ss;
    __syncthreads();
    if (t < 32) {
        float tot = 0.f;
        #pragma unroll
        for (int k = 0; k < 8; k++) tot += ssb[k][t];
        float inv = 1.0f / fmaxf(sqrtf(tot), 1e-12f);
        sinv[t] = inv;
        g_inv[b*Pn + p0 + t] = inv;
    }
    __syncthreads();
    int rowbase = b*Pn + p0;
    #pragma unroll
    for (int it = 0; it < 16; it++) {
        int id = it*256 + t;
        int pr = id >> 7, c2 = (id & 127)*2;
        float inv = sinv[pr];
        __nv_bfloat162 h = __floats2bfloat162_rn(tile[pr*257+c2]*inv, tile[pr*257+c2+1]*inv);
        *reinterpret_cast<__nv_bfloat162*>(g_vfb + (size_t)(rowbase+pr)*Cc + c2) = h;
    }
}

// ---------------- K2: iou2d mask bits ----------------
__global__ void k_iou(const float* __restrict__ iou2d) {
    int p = blockIdx.x*256 + threadIdx.x;
    int s = blockIdx.y;
    if (p < Pn)
        g_iou[s*Pn + p] = (iou2d[(size_t)s*NNe + g_flat[p]] > 0.5f) ? 1 : 0;
}

// ---------------- K3: per-chunk top-2 (phase 1), exact jax tie semantics ----------------
__device__ __forceinline__ bool better(float v, int i, float vx, int ix) {
    return v > vx || (v == vx && i < ix);
}
__global__ __launch_bounds__(128) void k_topk1(const float* __restrict__ iou2ds) {
    __shared__ float s1[128], s2[128];
    __shared__ int   i1s[128], i2s[128];
    int m = blockIdx.x, c = blockIdx.y, t = threadIdx.x;
    const float* row = iou2ds + (size_t)m*NNe;
    int pbase = c*CHUNK;

    float v[9]; int pi[9];
    #pragma unroll
    for (int it = 0; it < 9; it++) {
        int p = pbase + it*128 + t;
        pi[it] = p;
        v[it] = (it*128 + t < CHUNK) ? row[g_flat[p]] : -1e30f;
    }
    float v1 = -1e30f, v2 = -1e30f; int j1 = 0x7fffffff, j2 = 0x7fffffff;
    #pragma unroll
    for (int it = 0; it < 9; it++) {
        if (better(v[it], pi[it], v1, j1)) { v2=v1; j2=j1; v1=v[it]; j1=pi[it]; }
        else if (better(v[it], pi[it], v2, j2)) { v2=v[it]; j2=pi[it]; }
    }
    s1[t]=v1; i1s[t]=j1; s2[t]=v2; i2s[t]=j2;
    __syncthreads();
    for (int off = 64; off > 0; off >>= 1) {
        if (t < off) {
            float a1=s1[t], a2=s2[t], b1=s1[t+off], b2=s2[t+off];
            int   ai1=i1s[t], ai2=i2s[t], bi1=i1s[t+off], bi2=i2s[t+off];
            float r1, r2; int ri1, ri2;
            if (better(a1, ai1, b1, bi1)) {
                r1=a1; ri1=ai1;
                if (better(a2, ai2, b1, bi1)) { r2=a2; ri2=ai2; } else { r2=b1; ri2=bi1; }
            } else {
                r1=b1; ri1=bi1;
                if (better(a1, ai1, b2, bi2)) { r2=a1; ri2=ai1; } else { r2=b2; ri2=bi2; }
            }
            s1[t]=r1; i1s[t]=ri1; s2[t]=r2; i2s[t]=ri2;
        }
        __syncthreads();
    }
    if (t == 0) {
        g_cv[m*16 + c*2]     = s1[0]; g_ci[m*16 + c*2]     = i1s[0];
        g_cv[m*16 + c*2 + 1] = s2[0]; g_ci[m*16 + c*2 + 1] = i2s[0];
    }
}

// ---------------- K4: merge candidates + build pos rows ----------------
__global__ __launch_bounds__(256) void k_pos(const float* __restrict__ vf) {
    __shared__ int sj;
    int r = blockIdx.x, c = threadIdx.x;
    int m = r >> 1, k = r & 1;
    if (c == 0) {
        float v1=-1e30f, v2=-1e30f; int j1=0x7fffffff, j2=0x7fffffff;
        #pragma unroll
        for (int e = 0; e < 16; e++) {
            float v = g_cv[m*16 + e]; int i = g_ci[m*16 + e];
            if (better(v, i, v1, j1)) { v2=v1; j2=j1; v1=v; j1=i; }
            else if (better(v, i, v2, j2)) { v2=v; j2=i; }
        }
        sj = k ? j2 : j1;
    }
    __syncthreads();
    int j = sj;
    int b = m >> 3;
    int row = b*Pn + j;
    g_posb[r*Cc + c] = g_vfb[(size_t)row*Cc + c];
    g_posf[r*Cc + c] = vf[((size_t)b*Cc + c)*NNe + g_flat[j]] * g_inv[row];
}

// ---------------- K5: mma.sync GEMM + masked exp row-sum ----------------
// A (128x256, shared by all blocks) -> registers straight from gmem.
// B (64x256) -> smem via cp.async, XOR-8 swizzle. smem ~33KB -> 2-3 CTAs/SM.
__device__ __forceinline__ void ldm4(unsigned addr, unsigned &r0, unsigned &r1, unsigned &r2, unsigned &r3) {
    asm volatile("ldmatrix.sync.aligned.m8n8.x4.shared.b16 {%0,%1,%2,%3}, [%4];"
                 : "=r"(r0), "=r"(r1), "=r"(r2), "=r"(r3) : "r"(addr));
}
__device__ __forceinline__ void mma16816(float* c, unsigned a0, unsigned a1, unsigned a2, unsigned a3,
                                         unsigned b0, unsigned b1) {
    asm volatile("mma.sync.aligned.m16n8k16.row.col.f32.bf16.bf16.f32 "
                 "{%0,%1,%2,%3}, {%4,%5,%6,%7}, {%8,%9}, {%0,%1,%2,%3};"
                 : "+f"(c[0]), "+f"(c[1]), "+f"(c[2]), "+f"(c[3])
                 : "r"(a0), "r"(a1), "r"(a2), "r"(a3), "r"(b0), "r"(b1));
}
__device__ __forceinline__ void cp16(unsigned saddr, const void* gaddr) {
    asm volatile("cp.async.cg.shared.global [%0], [%1], 16;" :: "r"(saddr), "l"(gaddr));
}

__global__ __launch_bounds__(256) void k_gemm() {
    __shared__ __align__(16) __nv_bfloat16 sB[64*256];   // 32KB swizzled
    __shared__ unsigned char sI[4*64];

    int t = threadIdx.x;
    int w = t >> 5, l = t & 31;
    int gp0 = blockIdx.x * 64;
    int b   = gp0 / Pn;          // tile never straddles a video
    int j0  = gp0 - b*Pn;

    // B tile via cp.async (swizzled 16B chunks)
    {
        const char* gB = reinterpret_cast<const char*>(g_vfb + (size_t)(b*Pn + j0)*Cc);
        unsigned sb0 = (unsigned)__cvta_generic_to_shared(sB);
        #pragma unroll
        for (int it = 0; it < 8; it++) {
            int idx = it*256 + t;
            int row = idx >> 5, ch = idx & 31;
            cp16(sb0 + (row*32 + (ch ^ (row & 7)))*16, gB + row*512 + ch*16);
        }
        asm volatile("cp.async.commit_group;");
    }
    // iou bits: 4 sentences of this video x 64 cols
    if (t < 256) {
        int i = t;
        if (i < 4*64) {
            int ss = i >> 6, n = i & 63;
            sI[i] = g_iou[(b*4 + ss)*Pn + j0 + n];
        }
    }

    // A fragments straight from gmem (L2-hot, 64KB total) while cp.async flies
    int m0 = w * 16;
    int ra = m0 + (l >> 2);
    unsigned afrag[16][4];
    {
        const unsigned* gA = reinterpret_cast<const unsigned*>(g_posb); // row stride 128 words
        int cb = (l & 3);
        #pragma unroll
        for (int ks = 0; ks < 16; ks++) {
            int col = ks*8 + cb;
            afrag[ks][0] = gA[ra*128 + col];
            afrag[ks][1] = gA[(ra+8)*128 + col];
            afrag[ks][2] = gA[ra*128 + col + 4];
            afrag[ks][3] = gA[(ra+8)*128 + col + 4];
        }
    }

    float acc[8][4];
    #pragma unroll
    for (int i = 0; i < 8; i++)
        #pragma unroll
        for (int q = 0; q < 4; q++) acc[i][q] = 0.f;

    asm volatile("cp.async.wait_group 0;");
    __syncthreads();

    unsigned sb = (unsigned)__cvta_generic_to_shared(sB);
    int rowBbase = (l & 7) + ((l >> 4) & 1) * 8;
    int chSelB   = (l >> 3) & 1;

    #pragma unroll
    for (int ks = 0; ks < 16; ks++) {
        #pragma unroll
        for (int ntp = 0; ntp < 4; ntp++) {
            int rowB = ntp*16 + rowBbase;
            int chB  = 2*ks + chSelB;
            unsigned b0, b1, b2, b3;
            ldm4(sb + rowB*512 + (((chB ^ (rowB & 7)) & 31) << 4), b0, b1, b2, b3);
            mma16816(acc[ntp*2],     afrag[ks][0], afrag[ks][1], afrag[ks][2], afrag[ks][3], b0, b1);
            mma16816(acc[ntp*2 + 1], afrag[ks][0], afrag[ks][1], afrag[ks][2], afrag[ks][3], b2, b3);
        }
    }

    // epilogue: exp(dot/T), neg-mask, per-row partial sums
    const float K2E = 14.4269504088896340f;   // log2(e)/T
    int mr = l >> 2;
    int nb = (l & 3) * 2;
    int rLo = m0 + mr, rHi = rLo + 8;
    int siLo = ((rLo >> 2) & 3) * 64, siHi = ((rHi >> 2) & 3) * 64;
    bool own = (w == b);                       // rows' video == tile's video
    float sumLo = 0.f, sumHi = 0.f;
    #pragma unroll
    for (int nt = 0; nt < 8; nt++) {
        #pragma unroll
        for (int q = 0; q < 2; q++) {
            int n = nt*8 + nb + q;
            float eLo = fexp2(acc[nt][q]   * K2E);
            float eHi = fexp2(acc[nt][2+q] * K2E);
            bool mLo = own && sI[siLo + n];
            bool mHi = own && sI[siHi + n];
            sumLo += mLo ? 0.f : eLo;
            sumHi += mHi ? 0.f : eHi;
        }
    }
    sumLo += __shfl_xor_sync(0xffffffffu, sumLo, 1);
    sumLo += __shfl_xor_sync(0xffffffffu, sumLo, 2);
    sumHi += __shfl_xor_sync(0xffffffffu, sumHi, 1);
    sumHi += __shfl_xor_sync(0xffffffffu, sumHi, 2);
    if ((l & 3) == 0) {
        g_partial[blockIdx.x*RT + rLo] = sumLo;
        g_partial[blockIdx.x*RT + rHi] = sumHi;
    }
}

// ---------------- K6a: deterministic reduce ----------------
__global__ void k_negred() {
    int r = threadIdx.x;
    float s0 = 0, s1 = 0, s2 = 0, s3 = 0;
    for (int pb = 0; pb < NBLK; pb += 4) {
        s0 += g_partial[(pb+0)*RT + r];
        s1 += g_partial[(pb+1)*RT + r];
        s2 += g_partial[(pb+2)*RT + r];
        s3 += g_partial[(pb+3)*RT + r];
    }
    g_negsum[r] = (s0 + s1) + (s2 + s3);
}

// ---------------- K6b: per-sentence pair terms ----------------
__global__ void k_pairs() {
    __shared__ float sp[4*256];
    __shared__ float terms[16];
    int s = blockIdx.x, t = threadIdx.x;
    for (int i = t; i < 1024; i += 128) sp[i] = g_posf[s*4*256 + i];
    __syncthreads();
    int pair = t >> 3, cc = t & 7;
    int a_ref = pair >> 2, a_pos = pair & 3;
    float d = 0.f;
    #pragma unroll
    for (int k = 0; k < 32; k++) {
        int c = cc*32 + k;
        d += sp[a_ref*256 + c] * sp[a_pos*256 + c];
    }
    d += __shfl_xor_sync(0xffffffffu, d, 1);
    d += __shfl_xor_sync(0xffffffffu, d, 2);
    d += __shfl_xor_sync(0xffffffffu, d, 4);
    if (cc == 0) {
        float x = d * 10.0f;
        float ns = g_negsum[s*4 + a_ref];
        terms[pair] = -(x - logf(expf(x) + ns));
    }
    __syncthreads();
    if (t == 0) {
        float su = 0.f;
        #pragma unroll
        for (int i = 0; i < 16; i++) su += terms[i];
        g_ploss[s] = su;
    }
}

// ---------------- K6c: final mean ----------------
__global__ void k_final(float* out) {
    if (threadIdx.x == 0) {
        float su = 0.f;
        #pragma unroll
        for (int i = 0; i < Sv; i++) su += g_ploss[i];
        out[0] = su * (1.0f / 512.0f);
    }
}

// ---------------- launch ----------------
extern "C" void kernel_launch(void* const* d_in, const int* in_sizes, int n_in,
                              void* d_out, int out_size) {
    const float* video  = (const float*)d_in[0];
    const float* iou2d  = (const float*)d_in[4];
    const float* iou2ds = (const float*)d_in[5];
    float* out = (float*)d_out;

    k_flat<<<64, 256>>>();
    k_norm<<<dim3(Pn/32, Bv), 256>>>(video);
    k_iou<<<dim3(33, Sv), 256>>>(iou2d);
    k_topk1<<<dim3(Mv, 8), 128>>>(iou2ds);
    k_pos<<<RT, 256>>>(video);
    k_gemm<<<NBLK, 256>>>();
    k_negred<<<1, 128>>>();
    k_pairs<<<Sv, 128>>>();
    k_final<<<1, 32>>>(out);
}

// round 8
// speedup vs baseline: 1.4956x; 1.3865x over previous
#include <cuda_runtime.h>
#include <cuda_bf16.h>
#include <math.h>

// ---------------- problem constants ----------------
constexpr int Bv   = 8;      // videos
constexpr int Cc   = 256;    // feature dim
constexpr int Nn   = 128;    // N
constexpr int NNe  = Nn*Nn;  // 16384
constexpr int Sv   = 32;     // sentences
constexpr int Mv   = 64;     // moments
constexpr int Pn   = 8256;   // N*(N+1)/2 proposals
constexpr int BP   = Bv*Pn;  // 66048
constexpr int RT   = 128;    // pos rows = M*K
constexpr int NBLK = BP/64;  // 1032 GEMM column tiles (64 | P)

// ---------------- scratch ----------------
__device__ __align__(16) int            g_flat[Pn];
__device__ __align__(16) float          g_inv[BP];
__device__ __align__(16) __nv_bfloat16  g_vfb[(size_t)BP*Cc];
__device__ __align__(16) unsigned char  g_iou[Sv*Pn];
__device__ __align__(16) float          g_cv[Mv*16];
__device__ __align__(16) int            g_ci[Mv*16];
__device__ __align__(16) __nv_bfloat16  g_posb[RT*Cc];
__device__ __align__(16) float          g_posf[RT*Cc];
__device__ __align__(16) float          g_partial[RT*NBLK];   // [row][tile] transposed
__device__ __align__(16) float          g_negsum[RT];
__device__ __align__(16) float          g_ploss[Sv];

// ---------------- fast exp2 on FMA pipe ----------------
__device__ __forceinline__ float fexp2(float x) {
    float z = __fadd_rn(x, 12582912.0f);
    float f = __fsub_rn(x, __fsub_rn(z, 12582912.0f));
    int   e = __float_as_int(z) << 23;
    float p = 1.3333558146e-3f;
    p = __fmaf_rn(p, f, 9.6181291918e-3f);
    p = __fmaf_rn(p, f, 5.5504108664e-2f);
    p = __fmaf_rn(p, f, 2.4022650696e-1f);
    p = __fmaf_rn(p, f, 6.9314718056e-1f);
    p = __fmaf_rn(p, f, 1.0f);
    return __int_as_float(__float_as_int(p) + e);
}

// ---------------- K0: upper-tri flat index table ----------------
__global__ void k_flat() {
    int idx = blockIdx.x*256 + threadIdx.x;
    if (idx < NNe) {
        int i = idx >> 7, j = idx & 127;
        if (j >= i) g_flat[i*Nn - (i*(i-1))/2 + (j - i)] = idx;
    }
}

// ---------------- K1: gather + L2 norm + bf16 emit ----------------
__global__ __launch_bounds__(256) void k_norm(const float* __restrict__ vf) {
    __shared__ float tile[32*257];
    __shared__ float ssb[8][32];
    __shared__ float sinv[32];
    int b = blockIdx.y, p0 = blockIdx.x*32, t = threadIdx.x;
    int p = t & 31, c0 = t >> 5;
    int fi = g_flat[p0 + p];
    const float* base = vf + (size_t)b*Cc*NNe + fi;
    float ss = 0.f;
    #pragma unroll
    for (int k = 0; k < 32; k++) {
        int c = c0*32 + k;
        float v = base[(size_t)c*NNe];
        tile[p*257 + c] = v;
        ss += v*v;
    }
    ssb[c0][p] = ss;
    __syncthreads();
    if (t < 32) {
        float tot = 0.f;
        #pragma unroll
        for (int k = 0; k < 8; k++) tot += ssb[k][t];
        float inv = 1.0f / fmaxf(sqrtf(tot), 1e-12f);
        sinv[t] = inv;
        g_inv[b*Pn + p0 + t] = inv;
    }
    __syncthreads();
    int rowbase = b*Pn + p0;
    #pragma unroll
    for (int it = 0; it < 16; it++) {
        int id = it*256 + t;
        int pr = id >> 7, c2 = (id & 127)*2;
        float inv = sinv[pr];
        __nv_bfloat162 h = __floats2bfloat162_rn(tile[pr*257+c2]*inv, tile[pr*257+c2+1]*inv);
        *reinterpret_cast<__nv_bfloat162*>(g_vfb + (size_t)(rowbase+pr)*Cc + c2) = h;
    }
}

// ---------------- K2: iou2d mask bits (contiguous read, computed p) ----------------
__global__ void k_iou(const float* __restrict__ iou2d) {
    int idx = blockIdx.x*256 + threadIdx.x;   // flat position
    int s = blockIdx.y;
    int i = idx >> 7, j = idx & 127;
    if (j >= i) {
        int p = i*Nn - (i*(i-1))/2 + (j - i);
        g_iou[s*Pn + p] = (iou2d[(size_t)s*NNe + idx] > 0.5f) ? 1 : 0;
    }
}

// ---------------- K3: per-chunk top-2 over contiguous rows ----------------
__device__ __forceinline__ bool better(float v, int i, float vx, int ix) {
    return v > vx || (v == vx && i < ix);
}
__device__ __forceinline__ void top2upd(float v, int pidx, float& v1, int& j1, float& v2, int& j2) {
    if (better(v, pidx, v1, j1)) { v2=v1; j2=j1; v1=v; j1=pidx; }
    else if (better(v, pidx, v2, j2)) { v2=v; j2=pidx; }
}
__global__ __launch_bounds__(128) void k_topk1(const float* __restrict__ iou2ds) {
    __shared__ float s1[128], s2[128];
    __shared__ int   i1s[128], i2s[128];
    int m = blockIdx.x, c = blockIdx.y, t = threadIdx.x;
    const float4* row = reinterpret_cast<const float4*>(iou2ds + (size_t)m*NNe);
    int vbase = c*512;   // 8 chunks x 512 float4 = 4096 vecs

    float v1 = -1e30f, v2 = -1e30f; int j1 = 0x7fffffff, j2 = 0x7fffffff;
    #pragma unroll
    for (int it = 0; it < 4; it++) {
        int vi = vbase + it*128 + t;
        float4 f = row[vi];
        int flat = vi*4;
        #pragma unroll
        for (int q = 0; q < 4; q++) {
            float v = (q==0)?f.x:(q==1)?f.y:(q==2)?f.z:f.w;
            int fl = flat + q;
            int i = fl >> 7, j = fl & 127;
            bool valid = (j >= i);
            int p = i*Nn - (i*(i-1))/2 + (j - i);
            top2upd(valid ? v : -1e30f, valid ? p : 0x7fffffff, v1, j1, v2, j2);
        }
    }
    s1[t]=v1; i1s[t]=j1; s2[t]=v2; i2s[t]=j2;
    __syncthreads();
    for (int off = 64; off > 0; off >>= 1) {
        if (t < off) {
            float a1=s1[t], a2=s2[t], b1=s1[t+off], b2=s2[t+off];
            int   ai1=i1s[t], ai2=i2s[t], bi1=i1s[t+off], bi2=i2s[t+off];
            float r1, r2; int ri1, ri2;
            if (better(a1, ai1, b1, bi1)) {
                r1=a1; ri1=ai1;
                if (better(a2, ai2, b1, bi1)) { r2=a2; ri2=ai2; } else { r2=b1; ri2=bi1; }
            } else {
                r1=b1; ri1=bi1;
                if (better(a1, ai1, b2, bi2)) { r2=a1; ri2=ai1; } else { r2=b2; ri2=bi2; }
            }
            s1[t]=r1; i1s[t]=ri1; s2[t]=r2; i2s[t]=ri2;
        }
        __syncthreads();
    }
    if (t == 0) {
        g_cv[m*16 + c*2]     = s1[0]; g_ci[m*16 + c*2]     = i1s[0];
        g_cv[m*16 + c*2 + 1] = s2[0]; g_ci[m*16 + c*2 + 1] = i2s[0];
    }
}

// ---------------- K4: merge candidates + build pos rows ----------------
__global__ __launch_bounds__(256) void k_pos(const float* __restrict__ vf) {
    __shared__ int sj;
    int r = blockIdx.x, c = threadIdx.x;
    int m = r >> 1, k = r & 1;
    if (c == 0) {
        float v1=-1e30f, v2=-1e30f; int j1=0x7fffffff, j2=0x7fffffff;
        #pragma unroll
        for (int e = 0; e < 16; e++) {
            float v = g_cv[m*16 + e]; int i = g_ci[m*16 + e];
            if (better(v, i, v1, j1)) { v2=v1; j2=j1; v1=v; j1=i; }
            else if (better(v, i, v2, j2)) { v2=v; j2=i; }
        }
        sj = k ? j2 : j1;
    }
    __syncthreads();
    int j = sj;
    int b = m >> 3;
    int row = b*Pn + j;
    g_posb[r*Cc + c] = g_vfb[(size_t)row*Cc + c];
    g_posf[r*Cc + c] = vf[((size_t)b*Cc + c)*NNe + g_flat[j]] * g_inv[row];
}

// ---------------- K5: mma.sync GEMM + masked exp row-sum ----------------
__device__ __forceinline__ void ldm4(unsigned addr, unsigned &r0, unsigned &r1, unsigned &r2, unsigned &r3) {
    asm volatile("ldmatrix.sync.aligned.m8n8.x4.shared.b16 {%0,%1,%2,%3}, [%4];"
                 : "=r"(r0), "=r"(r1), "=r"(r2), "=r"(r3) : "r"(addr));
}
__device__ __forceinline__ void mma16816(float* c, unsigned a0, unsigned a1, unsigned a2, unsigned a3,
                                         unsigned b0, unsigned b1) {
    asm volatile("mma.sync.aligned.m16n8k16.row.col.f32.bf16.bf16.f32 "
                 "{%0,%1,%2,%3}, {%4,%5,%6,%7}, {%8,%9}, {%0,%1,%2,%3};"
                 : "+f"(c[0]), "+f"(c[1]), "+f"(c[2]), "+f"(c[3])
                 : "r"(a0), "r"(a1), "r"(a2), "r"(a3), "r"(b0), "r"(b1));
}
__device__ __forceinline__ void cp16(unsigned saddr, const void* gaddr) {
    asm volatile("cp.async.cg.shared.global [%0], [%1], 16;" :: "r"(saddr), "l"(gaddr));
}

// A-fragments halved (32 regs live) so 2 CTAs/SM fit; half-1 reloaded mid-compute.
__global__ __launch_bounds__(256, 2) void k_gemm() {
    __shared__ __align__(16) __nv_bfloat16 sB[64*256];   // 32KB swizzled
    __shared__ unsigned char sI[4*64];

    int t = threadIdx.x;
    int w = t >> 5, l = t & 31;
    int gp0 = blockIdx.x * 64;
    int b   = gp0 / Pn;
    int j0  = gp0 - b*Pn;

    // B tile via cp.async (swizzled 16B chunks)
    {
        const char* gB = reinterpret_cast<const char*>(g_vfb + (size_t)(b*Pn + j0)*Cc);
        unsigned sb0 = (unsigned)__cvta_generic_to_shared(sB);
        #pragma unroll
        for (int it = 0; it < 8; it++) {
            int idx = it*256 + t;
            int row = idx >> 5, ch = idx & 31;
            cp16(sb0 + (row*32 + (ch ^ (row & 7)))*16, gB + row*512 + ch*16);
        }
        asm volatile("cp.async.commit_group;");
    }
    // iou bits: 4 sentences of this video x 64 cols
    {
        int ss = t >> 6, n = t & 63;
        sI[t] = g_iou[(b*4 + ss)*Pn + j0 + n];
    }

    int m0 = w * 16;
    int ra = m0 + (l >> 2);
    int cb = (l & 3);
    const unsigned* gA = reinterpret_cast<const unsigned*>(g_posb); // row stride 128 words

    unsigned af[8][4];
    #pragma unroll
    for (int ks = 0; ks < 8; ks++) {
        int col = ks*8 + cb;
        af[ks][0] = gA[ra*128 + col];
        af[ks][1] = gA[(ra+8)*128 + col];
        af[ks][2] = gA[ra*128 + col + 4];
        af[ks][3] = gA[(ra+8)*128 + col + 4];
    }

    float acc[8][4];
    #pragma unroll
    for (int i = 0; i < 8; i++)
        #pragma unroll
        for (int q = 0; q < 4; q++) acc[i][q] = 0.f;

    asm volatile("cp.async.wait_group 0;");
    __syncthreads();

    unsigned sb = (unsigned)__cvta_generic_to_shared(sB);
    int rowBbase = (l & 7) + ((l >> 4) & 1) * 8;
    int chSelB   = (l >> 3) & 1;

    #pragma unroll
    for (int ks = 0; ks < 8; ks++) {
        #pragma unroll
        for (int ntp = 0; ntp < 4; ntp++) {
            int rowB = ntp*16 + rowBbase;
            int chB  = 2*ks + chSelB;
            unsigned b0, b1, b2, b3;
            ldm4(sb + rowB*512 + (((chB ^ (rowB & 7)) & 31) << 4), b0, b1, b2, b3);
            mma16816(acc[ntp*2],     af[ks][0], af[ks][1], af[ks][2], af[ks][3], b0, b1);
            mma16816(acc[ntp*2 + 1], af[ks][0], af[ks][1], af[ks][2], af[ks][3], b2, b3);
        }
    }
    // reload half-1 A fragments (batched -> high MLP; other CTA hides latency)
    #pragma unroll
    for (int ks = 0; ks < 8; ks++) {
        int col = (ks + 8)*8 + cb;
        af[ks][0] = gA[ra*128 + col];
        af[ks][1] = gA[(ra+8)*128 + col];
        af[ks][2] = gA[ra*128 + col + 4];
        af[ks][3] = gA[(ra+8)*128 + col + 4];
    }
    #pragma unroll
    for (int ks = 0; ks < 8; ks++) {
        #pragma unroll
        for (int ntp = 0; ntp < 4; ntp++) {
            int rowB = ntp*16 + rowBbase;
            int chB  = 2*(ks + 8) + chSelB;
            unsigned b0, b1, b2, b3;
            ldm4(sb + rowB*512 + (((chB ^ (rowB & 7)) & 31) << 4), b0, b1, b2, b3);
            mma16816(acc[ntp*2],     af[ks][0], af[ks][1], af[ks][2], af[ks][3], b0, b1);
            mma16816(acc[ntp*2 + 1], af[ks][0], af[ks][1], af[ks][2], af[ks][3], b2, b3);
        }
    }

    // epilogue: exp(dot/T), neg-mask, per-row partial sums
    const float K2E = 14.4269504088896340f;   // log2(e)/T
    int mr = l >> 2;
    int nb = (l & 3) * 2;
    int rLo = m0 + mr, rHi = rLo + 8;
    int siLo = ((rLo >> 2) & 3) * 64, siHi = ((rHi >> 2) & 3) * 64;
    bool own = (w == b);
    float sumLo = 0.f, sumHi = 0.f;
    #pragma unroll
    for (int nt = 0; nt < 8; nt++) {
        #pragma unroll
        for (int q = 0; q < 2; q++) {
            int n = nt*8 + nb + q;
            float eLo = fexp2(acc[nt][q]   * K2E);
            float eHi = fexp2(acc[nt][2+q] * K2E);
            bool mLo = own && sI[siLo + n];
            bool mHi = own && sI[siHi + n];
            sumLo += mLo ? 0.f : eLo;
            sumHi += mHi ? 0.f : eHi;
        }
    }
    sumLo += __shfl_xor_sync(0xffffffffu, sumLo, 1);
    sumLo += __shfl_xor_sync(0xffffffffu, sumLo, 2);
    sumHi += __shfl_xor_sync(0xffffffffu, sumHi, 1);
    sumHi += __shfl_xor_sync(0xffffffffu, sumHi, 2);
    if ((l & 3) == 0) {
        g_partial[rLo*NBLK + blockIdx.x] = sumLo;   // transposed: coalesced reduce
        g_partial[rHi*NBLK + blockIdx.x] = sumHi;
    }
}

// ---------------- K6a: parallel deterministic reduce (coalesced rows) ----------------
__global__ __launch_bounds__(256) void k_negred() {
    __shared__ float sm[256];
    int r = blockIdx.x, t = threadIdx.x;
    float s = 0.f;
    for (int k = t; k < NBLK; k += 256) s += g_partial[r*NBLK + k];
    sm[t] = s; __syncthreads();
    for (int off = 128; off > 0; off >>= 1) {
        if (t < off) sm[t] += sm[t+off];
        __syncthreads();
    }
    if (t == 0) g_negsum[r] = sm[0];
}

// ---------------- K6b: per-sentence pair terms ----------------
__global__ void k_pairs() {
    __shared__ float sp[4*256];
    __shared__ float terms[16];
    int s = blockIdx.x, t = threadIdx.x;
    for (int i = t; i < 1024; i += 128) sp[i] = g_posf[s*4*256 + i];
    __syncthreads();
    int pair = t >> 3, cc = t & 7;
    int a_ref = pair >> 2, a_pos = pair & 3;
    float d = 0.f;
    #pragma unroll
    for (int k = 0; k < 32; k++) {
        int c = cc*32 + k;
        d += sp[a_ref*256 + c] * sp[a_pos*256 + c];
    }
    d += __shfl_xor_sync(0xffffffffu, d, 1);
    d += __shfl_xor_sync(0xffffffffu, d, 2);
    d += __shfl_xor_sync(0xffffffffu, d, 4);
    if (cc == 0) {
        float x = d * 10.0f;
        float ns = g_negsum[s*4 + a_ref];
        terms[pair] = -(x - logf(expf(x) + ns));
    }
    __syncthreads();
    if (t == 0) {
        float su = 0.f;
        #pragma unroll
        for (int i = 0; i < 16; i++) su += terms[i];
        g_ploss[s] = su;
    }
}

// ---------------- K6c: final mean ----------------
__global__ void k_final(float* out) {
    if (threadIdx.x == 0) {
        float su = 0.f;
        #pragma unroll
        for (int i = 0; i < Sv; i++) su += g_ploss[i];
        out[0] = su * (1.0f / 512.0f);
    }
}

// ---------------- launch ----------------
extern "C" void kernel_launch(void* const* d_in, const int* in_sizes, int n_in,
                              void* d_out, int out_size) {
    const float* video  = (const float*)d_in[0];
    const float* iou2d  = (const float*)d_in[4];
    const float* iou2ds = (const float*)d_in[5];
    float* out = (float*)d_out;

    k_flat<<<64, 256>>>();
    k_norm<<<dim3(Pn/32, Bv), 256>>>(video);
    k_iou<<<dim3(64, Sv), 256>>>(iou2d);
    k_topk1<<<dim3(Mv, 8), 128>>>(iou2ds);
    k_pos<<<RT, 256>>>(video);
    k_gemm<<<NBLK, 256>>>();
    k_negred<<<RT, 256>>>();
    k_pairs<<<Sv, 128>>>();
    k_final<<<1, 32>>>(out);
}

// round 9
// speedup vs baseline: 1.6405x; 1.0969x over previous
#include <cuda_runtime.h>
#include <cuda_bf16.h>
#include <math.h>

// ---------------- problem constants ----------------
constexpr int Bv   = 8;      // videos
constexpr int Cc   = 256;    // feature dim
constexpr int Nn   = 128;    // N
constexpr int NNe  = Nn*Nn;  // 16384
constexpr int Sv   = 32;     // sentences
constexpr int Mv   = 64;     // moments
constexpr int Pn   = 8256;   // N*(N+1)/2 proposals
constexpr int BP   = Bv*Pn;  // 66048
constexpr int RT   = 128;    // pos rows = M*K
constexpr int NBLK = BP/64;  // 1032 GEMM column tiles (64 | P)
constexpr int GRID = 296;    // persistent GEMM CTAs (2 per SM x 148)

// ---------------- scratch ----------------
__device__ __align__(16) int            g_flat[Pn];
__device__ __align__(16) float          g_inv[BP];
__device__ __align__(16) __nv_bfloat16  g_vfb[(size_t)BP*Cc];
__device__ __align__(16) unsigned char  g_iou[Sv*Pn];
__device__ __align__(16) float          g_cv[Mv*16];
__device__ __align__(16) int            g_ci[Mv*16];
__device__ __align__(16) __nv_bfloat16  g_posb[RT*Cc];
__device__ __align__(16) float          g_posf[RT*Cc];
__device__ __align__(16) float          g_partial[RT*NBLK];   // [row][tile]
__device__ __align__(16) float          g_negsum[RT];
__device__ __align__(16) float          g_ploss[Sv];

// ---------------- fast exp2 on FMA pipe ----------------
__device__ __forceinline__ float fexp2(float x) {
    float z = __fadd_rn(x, 12582912.0f);
    float f = __fsub_rn(x, __fsub_rn(z, 12582912.0f));
    int   e = __float_as_int(z) << 23;
    float p = 1.3333558146e-3f;
    p = __fmaf_rn(p, f, 9.6181291918e-3f);
    p = __fmaf_rn(p, f, 5.5504108664e-2f);
    p = __fmaf_rn(p, f, 2.4022650696e-1f);
    p = __fmaf_rn(p, f, 6.9314718056e-1f);
    p = __fmaf_rn(p, f, 1.0f);
    return __int_as_float(__float_as_int(p) + e);
}

// ---------------- K0: upper-tri flat index table ----------------
__global__ void k_flat() {
    int idx = blockIdx.x*256 + threadIdx.x;
    if (idx < NNe) {
        int i = idx >> 7, j = idx & 127;
        if (j >= i) g_flat[i*Nn - (i*(i-1))/2 + (j - i)] = idx;
    }
}

// ---------------- K1: gather + L2 norm + bf16 emit ----------------
__global__ __launch_bounds__(256) void k_norm(const float* __restrict__ vf) {
    __shared__ float tile[32*257];
    __shared__ float ssb[8][32];
    __shared__ float sinv[32];
    int b = blockIdx.y, p0 = blockIdx.x*32, t = threadIdx.x;
    int p = t & 31, c0 = t >> 5;
    int fi = g_flat[p0 + p];
    const float* base = vf + (size_t)b*Cc*NNe + fi;
    float ss = 0.f;
    #pragma unroll
    for (int k = 0; k < 32; k++) {
        int c = c0*32 + k;
        float v = base[(size_t)c*NNe];
        tile[p*257 + c] = v;
        ss += v*v;
    }
    ssb[c0][p] = ss;
    __syncthreads();
    if (t < 32) {
        float tot = 0.f;
        #pragma unroll
        for (int k = 0; k < 8; k++) tot += ssb[k][t];
        float inv = 1.0f / fmaxf(sqrtf(tot), 1e-12f);
        sinv[t] = inv;
        g_inv[b*Pn + p0 + t] = inv;
    }
    __syncthreads();
    int rowbase = b*Pn + p0;
    #pragma unroll
    for (int it = 0; it < 16; it++) {
        int id = it*256 + t;
        int pr = id >> 7, c2 = (id & 127)*2;
        float inv = sinv[pr];
        __nv_bfloat162 h = __floats2bfloat162_rn(tile[pr*257+c2]*inv, tile[pr*257+c2+1]*inv);
        *reinterpret_cast<__nv_bfloat162*>(g_vfb + (size_t)(rowbase+pr)*Cc + c2) = h;
    }
}

// ---------------- K2: iou2d mask bits (contiguous read, computed p) ----------------
__global__ void k_iou(const float* __restrict__ iou2d) {
    int idx = blockIdx.x*256 + threadIdx.x;
    int s = blockIdx.y;
    int i = idx >> 7, j = idx & 127;
    if (j >= i) {
        int p = i*Nn - (i*(i-1))/2 + (j - i);
        g_iou[s*Pn + p] = (iou2d[(size_t)s*NNe + idx] > 0.5f) ? 1 : 0;
    }
}

// ---------------- K3: quarter-row top-2, warp shfl merge ----------------
__device__ __forceinline__ bool better(float v, int i, float vx, int ix) {
    return v > vx || (v == vx && i < ix);
}
__device__ __forceinline__ void top2upd(float v, int pidx, float& v1, int& j1, float& v2, int& j2) {
    if (better(v, pidx, v1, j1)) { v2=v1; j2=j1; v1=v; j1=pidx; }
    else if (better(v, pidx, v2, j2)) { v2=v; j2=pidx; }
}
__global__ __launch_bounds__(256) void k_topk1(const float* __restrict__ iou2ds) {
    __shared__ float scv[16];
    __shared__ int   sci[16];
    int m = blockIdx.x, q = blockIdx.y, t = threadIdx.x;
    int w = t >> 5, l = t & 31;
    const float4* row = reinterpret_cast<const float4*>(iou2ds + (size_t)m*NNe);

    float v1 = -1e30f, v2 = -1e30f; int j1 = 0x7fffffff, j2 = 0x7fffffff;
    #pragma unroll
    for (int it = 0; it < 4; it++) {
        int vi = q*1024 + it*256 + t;
        float4 f = row[vi];
        int flat = vi*4;
        #pragma unroll
        for (int qq = 0; qq < 4; qq++) {
            float v = (qq==0)?f.x:(qq==1)?f.y:(qq==2)?f.z:f.w;
            int fl = flat + qq;
            int i = fl >> 7, j = fl & 127;
            bool valid = (j >= i);
            int p = i*Nn - (i*(i-1))/2 + (j - i);
            top2upd(valid ? v : -1e30f, valid ? p : 0x7fffffff, v1, j1, v2, j2);
        }
    }
    // warp merge
    #pragma unroll
    for (int off = 16; off > 0; off >>= 1) {
        float o1 = __shfl_xor_sync(0xffffffffu, v1, off);
        int   oj1= __shfl_xor_sync(0xffffffffu, j1, off);
        float o2 = __shfl_xor_sync(0xffffffffu, v2, off);
        int   oj2= __shfl_xor_sync(0xffffffffu, j2, off);
        if (better(o1, oj1, v1, j1)) {
            if (better(v1, j1, o2, oj2)) { v2=v1; j2=j1; } else { v2=o2; j2=oj2; }
            v1=o1; j1=oj1;
        } else if (better(o1, oj1, v2, j2)) { v2=o1; j2=oj1; }
    }
    if (l == 0) { scv[w*2]=v1; sci[w*2]=j1; scv[w*2+1]=v2; sci[w*2+1]=j2; }
    __syncthreads();
    if (t == 0) {
        float b1=-1e30f, b2=-1e30f; int bi1=0x7fffffff, bi2=0x7fffffff;
        #pragma unroll
        for (int e = 0; e < 16; e++) top2upd(scv[e], sci[e], b1, bi1, b2, bi2);
        g_cv[m*16 + q*2]     = b1; g_ci[m*16 + q*2]     = bi1;
        g_cv[m*16 + q*2 + 1] = b2; g_ci[m*16 + q*2 + 1] = bi2;
    }
}

// ---------------- K4: merge candidates + build pos rows ----------------
__global__ __launch_bounds__(256) void k_pos(const float* __restrict__ vf) {
    __shared__ int sj;
    int r = blockIdx.x, c = threadIdx.x;
    int m = r >> 1, k = r & 1;
    if (c == 0) {
        float v1=-1e30f, v2=-1e30f; int j1=0x7fffffff, j2=0x7fffffff;
        #pragma unroll
        for (int e = 0; e < 8; e++) {   // 4 quarters x 2 candidates
            float v = g_cv[m*16 + e]; int i = g_ci[m*16 + e];
            if (better(v, i, v1, j1)) { v2=v1; j2=j1; v1=v; j1=i; }
            else if (better(v, i, v2, j2)) { v2=v; j2=i; }
        }
        sj = k ? j2 : j1;
    }
    __syncthreads();
    int j = sj;
    int b = m >> 3;
    int row = b*Pn + j;
    g_posb[r*Cc + c] = g_vfb[(size_t)row*Cc + c];
    g_posf[r*Cc + c] = vf[((size_t)b*Cc + c)*NNe + g_flat[j]] * g_inv[row];
}

// ---------------- K5: persistent mma.sync GEMM + masked exp row-sum ----------------
__device__ __forceinline__ void ldm4(unsigned addr, unsigned &r0, unsigned &r1, unsigned &r2, unsigned &r3) {
    asm volatile("ldmatrix.sync.aligned.m8n8.x4.shared.b16 {%0,%1,%2,%3}, [%4];"
                 : "=r"(r0), "=r"(r1), "=r"(r2), "=r"(r3) : "r"(addr));
}
__device__ __forceinline__ void mma16816(float* c, unsigned a0, unsigned a1, unsigned a2, unsigned a3,
                                         unsigned b0, unsigned b1) {
    asm volatile("mma.sync.aligned.m16n8k16.row.col.f32.bf16.bf16.f32 "
                 "{%0,%1,%2,%3}, {%4,%5,%6,%7}, {%8,%9}, {%0,%1,%2,%3};"
                 : "+f"(c[0]), "+f"(c[1]), "+f"(c[2]), "+f"(c[3])
                 : "r"(a0), "r"(a1), "r"(a2), "r"(a3), "r"(b0), "r"(b1));
}
__device__ __forceinline__ void cp16(unsigned saddr, const void* gaddr) {
    asm volatile("cp.async.cg.shared.global [%0], [%1], 16;" :: "r"(saddr), "l"(gaddr));
}

// dynamic smem: B0 [0,32K), B1 [32K,64K), iou0 [64K,+256), iou1 [+256,+512)
constexpr int SMEM_GEMM = 65536 + 512;

__global__ __launch_bounds__(256, 2) void k_gemm() {
    extern __shared__ __align__(16) unsigned char dsm[];
    unsigned sb0 = (unsigned)__cvta_generic_to_shared(dsm);
    unsigned char* sIg = dsm + 65536;

    int t = threadIdx.x;
    int w = t >> 5, l = t & 31;

    // ---- A fragments: loaded ONCE per persistent CTA (L2-hot 64KB table) ----
    int m0 = w * 16;
    int ra = m0 + (l >> 2);
    int cb = (l & 3);
    const unsigned* gA = reinterpret_cast<const unsigned*>(g_posb);
    unsigned af[16][4];
    #pragma unroll
    for (int ks = 0; ks < 16; ks++) {
        int col = ks*8 + cb;
        af[ks][0] = gA[ra*128 + col];
        af[ks][1] = gA[(ra+8)*128 + col];
        af[ks][2] = gA[ra*128 + col + 4];
        af[ks][3] = gA[(ra+8)*128 + col + 4];
    }

    // ---- prefetch first tile ----
    int tile0 = blockIdx.x;
    {
        const char* gB = reinterpret_cast<const char*>(g_vfb + (size_t)tile0*64*Cc);
        #pragma unroll
        for (int it = 0; it < 8; it++) {
            int idx = it*256 + t;
            int row = idx >> 5, ch = idx & 31;
            cp16(sb0 + (row*32 + (ch ^ (row & 7)))*16, gB + row*512 + ch*16);
        }
        int b0v = (tile0*64)/Pn, j00 = tile0*64 - b0v*Pn;
        sIg[t] = g_iou[(b0v*4 + (t >> 6))*Pn + j00 + (t & 63)];
        asm volatile("cp.async.commit_group;");
    }

    int rowBbase = (l & 7) + ((l >> 4) & 1) * 8;
    int chSelB   = (l >> 3) & 1;
    const float K2E = 14.4269504088896340f;
    int mr = l >> 2;
    int nb = (l & 3) * 2;
    int rLo = m0 + mr, rHi = rLo + 8;
    int siLo = ((rLo >> 2) & 3) * 64, siHi = ((rHi >> 2) & 3) * 64;

    int cur = 0;
    for (int tile = tile0; tile < NBLK; tile += GRID) {
        int nt = tile + GRID;
        bool hn = nt < NBLK;
        if (hn) {
            const char* gB = reinterpret_cast<const char*>(g_vfb + (size_t)nt*64*Cc);
            unsigned base = sb0 + (cur ^ 1)*32768;
            #pragma unroll
            for (int it = 0; it < 8; it++) {
                int idx = it*256 + t;
                int row = idx >> 5, ch = idx & 31;
                cp16(base + (row*32 + (ch ^ (row & 7)))*16, gB + row*512 + ch*16);
            }
            int bn = (nt*64)/Pn, j0n = nt*64 - bn*Pn;
            sIg[(cur ^ 1)*256 + t] = g_iou[(bn*4 + (t >> 6))*Pn + j0n + (t & 63)];
            asm volatile("cp.async.commit_group;");
            asm volatile("cp.async.wait_group 1;");
        } else {
            asm volatile("cp.async.wait_group 0;");
        }
        __syncthreads();

        int b = (tile*64)/Pn;
        unsigned sb = sb0 + cur*32768;
        const unsigned char* sI = sIg + cur*256;

        float acc[8][4];
        #pragma unroll
        for (int i = 0; i < 8; i++)
            #pragma unroll
            for (int q = 0; q < 4; q++) acc[i][q] = 0.f;

        #pragma unroll
        for (int ks = 0; ks < 16; ks++) {
            #pragma unroll
            for (int ntp = 0; ntp < 4; ntp++) {
                int rowB = ntp*16 + rowBbase;
                int chB  = 2*ks + chSelB;
                unsigned b0, b1, b2, b3;
                ldm4(sb + rowB*512 + (((chB ^ (rowB & 7)) & 31) << 4), b0, b1, b2, b3);
                mma16816(acc[ntp*2],     af[ks][0], af[ks][1], af[ks][2], af[ks][3], b0, b1);
                mma16816(acc[ntp*2 + 1], af[ks][0], af[ks][1], af[ks][2], af[ks][3], b2, b3);
            }
        }

        bool own = (w == b);
        float sumLo = 0.f, sumHi = 0.f;
        #pragma unroll
        for (int nt2 = 0; nt2 < 8; nt2++) {
            #pragma unroll
            for (int q = 0; q < 2; q++) {
                int n = nt2*8 + nb + q;
                float eLo = fexp2(acc[nt2][q]   * K2E);
                float eHi = fexp2(acc[nt2][2+q] * K2E);
                bool mLo = own && sI[siLo + n];
                bool mHi = own && sI[siHi + n];
                sumLo += mLo ? 0.f : eLo;
                sumHi += mHi ? 0.f : eHi;
            }
        }
        sumLo += __shfl_xor_sync(0xffffffffu, sumLo, 1);
        sumLo += __shfl_xor_sync(0xffffffffu, sumLo, 2);
        sumHi += __shfl_xor_sync(0xffffffffu, sumHi, 1);
        sumHi += __shfl_xor_sync(0xffffffffu, sumHi, 2);
        if ((l & 3) == 0) {
            g_partial[rLo*NBLK + tile] = sumLo;
            g_partial[rHi*NBLK + tile] = sumHi;
        }
        __syncthreads();   // all warps done reading buf before next prefetch reuses it
        cur ^= 1;
    }
}

// ---------------- K6a: parallel deterministic reduce ----------------
__global__ __launch_bounds__(256) void k_negred() {
    __shared__ float sm[256];
    int r = blockIdx.x, t = threadIdx.x;
    float s = 0.f;
    for (int k = t; k < NBLK; k += 256) s += g_partial[r*NBLK + k];
    sm[t] = s; __syncthreads();
    for (int off = 128; off > 0; off >>= 1) {
        if (t < off) sm[t] += sm[t+off];
        __syncthreads();
    }
    if (t == 0) g_negsum[r] = sm[0];
}

// ---------------- K6b: per-sentence pair terms ----------------
__global__ void k_pairs() {
    __shared__ float sp[4*256];
    __shared__ float terms[16];
    int s = blockIdx.x, t = threadIdx.x;
    for (int i = t; i < 1024; i += 128) sp[i] = g_posf[s*4*256 + i];
    __syncthreads();
    int pair = t >> 3, cc = t & 7;
    int a_ref = pair >> 2, a_pos = pair & 3;
    float d = 0.f;
    #pragma unroll
    for (int k = 0; k < 32; k++) {
        int c = cc*32 + k;
        d += sp[a_ref*256 + c] * sp[a_pos*256 + c];
    }
    d += __shfl_xor_sync(0xffffffffu, d, 1);
    d += __shfl_xor_sync(0xffffffffu, d, 2);
    d += __shfl_xor_sync(0xffffffffu, d, 4);
    if (cc == 0) {
        float x = d * 10.0f;
        float ns = g_negsum[s*4 + a_ref];
        terms[pair] = -(x - logf(expf(x) + ns));
    }
    __syncthreads();
    if (t == 0) {
        float su = 0.f;
        #pragma unroll
        for (int i = 0; i < 16; i++) su += terms[i];
        g_ploss[s] = su;
    }
}

// ---------------- K6c: final mean ----------------
__global__ void k_final(float* out) {
    if (threadIdx.x == 0) {
        float su = 0.f;
        #pragma unroll
        for (int i = 0; i < Sv; i++) su += g_ploss[i];
        out[0] = su * (1.0f / 512.0f);
    }
}

// ---------------- launch ----------------
extern "C" void kernel_launch(void* const* d_in, const int* in_sizes, int n_in,
                              void* d_out, int out_size) {
    const float* video  = (const float*)d_in[0];
    const float* iou2d  = (const float*)d_in[4];
    const float* iou2ds = (const float*)d_in[5];
    float* out = (float*)d_out;

    cudaFuncSetAttribute(k_gemm, cudaFuncAttributeMaxDynamicSharedMemorySize, SMEM_GEMM);

    k_flat<<<64, 256>>>();
    k_norm<<<dim3(Pn/32, Bv), 256>>>(video);
    k_iou<<<dim3(64, Sv), 256>>>(iou2d);
    k_topk1<<<dim3(Mv, 4), 256>>>(iou2ds);
    k_pos<<<RT, 256>>>(video);
    k_gemm<<<GRID, 256, SMEM_GEMM>>>();
    k_negred<<<RT, 256>>>();
    k_pairs<<<Sv, 128>>>();
    k_final<<<1, 32>>>(out);
}

// round 10
// speedup vs baseline: 1.7357x; 1.0580x over previous
#include <cuda_runtime.h>
#include <cuda_bf16.h>
#include <math.h>

// ---------------- problem constants ----------------
constexpr int Bv   = 8;      // videos
constexpr int Cc   = 256;    // feature dim
constexpr int Nn   = 128;    // N
constexpr int NNe  = Nn*Nn;  // 16384
constexpr int Sv   = 32;     // sentences
constexpr int Mv   = 64;     // moments
constexpr int Pn   = 8256;   // N*(N+1)/2 proposals
constexpr int BP   = Bv*Pn;  // 66048
constexpr int RT   = 128;    // pos rows = M*K
constexpr int NBLK = BP/64;  // 1032 GEMM column tiles (64 | P)
constexpr int GRID = 296;    // persistent GEMM CTAs (2 per SM x 148)

// ---------------- scratch ----------------
__device__ __align__(16) int            g_flat[Pn];
__device__ __align__(16) float          g_inv[BP];
__device__ __align__(16) __nv_bfloat16  g_vfb[(size_t)BP*Cc];
__device__ __align__(16) unsigned char  g_iou[Sv*Pn];
__device__ __align__(16) float          g_cv[Mv*16];
__device__ __align__(16) int            g_ci[Mv*16];
__device__ __align__(16) __nv_bfloat16  g_posb[RT*Cc];
__device__ __align__(16) float          g_posf[RT*Cc];
__device__ __align__(16) float          g_partial[RT*NBLK];   // [row][tile]
__device__ __align__(16) float          g_ploss[Sv];

// ---------------- fast exp2 on FMA pipe ----------------
__device__ __forceinline__ float fexp2(float x) {
    float z = __fadd_rn(x, 12582912.0f);
    float f = __fsub_rn(x, __fsub_rn(z, 12582912.0f));
    int   e = __float_as_int(z) << 23;
    float p = 1.3333558146e-3f;
    p = __fmaf_rn(p, f, 9.6181291918e-3f);
    p = __fmaf_rn(p, f, 5.5504108664e-2f);
    p = __fmaf_rn(p, f, 2.4022650696e-1f);
    p = __fmaf_rn(p, f, 6.9314718056e-1f);
    p = __fmaf_rn(p, f, 1.0f);
    return __int_as_float(__float_as_int(p) + e);
}

// ---------------- top-2 helpers (jax.lax.top_k tie semantics) ----------------
__device__ __forceinline__ bool better(float v, int i, float vx, int ix) {
    return v > vx || (v == vx && i < ix);
}
__device__ __forceinline__ void top2upd(float v, int pidx, float& v1, int& j1, float& v2, int& j2) {
    if (better(v, pidx, v1, j1)) { v2=v1; j2=j1; v1=v; j1=pidx; }
    else if (better(v, pidx, v2, j2)) { v2=v; j2=pidx; }
}

// ---------------- K1 (fused pre): flat table + iou bits + per-half top-2 ----------------
// blocks [0,64): flat table
// blocks [64,2112): iou mask (s = (bid-64)/64, 256 flat positions each)
// blocks [2112,2240): topk, one half-row of one moment per block
__global__ __launch_bounds__(256) void k_pre(const float* __restrict__ iou2d,
                                             const float* __restrict__ iou2ds) {
    __shared__ float scv[16];
    __shared__ int   sci[16];
    int bid = blockIdx.x, t = threadIdx.x;

    if (bid < 64) {
        int idx = bid*256 + t;
        int i = idx >> 7, j = idx & 127;
        if (j >= i) g_flat[i*Nn - (i*(i-1))/2 + (j - i)] = idx;
        return;
    }
    if (bid < 64 + 2048) {
        int r = bid - 64;
        int s = r >> 6;
        int idx = (r & 63)*256 + t;
        int i = idx >> 7, j = idx & 127;
        if (j >= i) {
            int p = i*Nn - (i*(i-1))/2 + (j - i);
            g_iou[s*Pn + p] = (iou2d[(size_t)s*NNe + idx] > 0.5f) ? 1 : 0;
        }
        return;
    }
    // ---- topk: 128 blocks, m = idx>>1, half = idx&1, MLP=8 ----
    int r = bid - 2112;
    int m = r >> 1, half = r & 1;
    int w = t >> 5, l = t & 31;
    const float4* row = reinterpret_cast<const float4*>(iou2ds + (size_t)m*NNe);

    float4 f[8];
    int vb = half*2048 + t;
    #pragma unroll
    for (int it = 0; it < 8; it++) f[it] = row[vb + it*256];

    float v1 = -1e30f, v2 = -1e30f; int j1 = 0x7fffffff, j2 = 0x7fffffff;
    #pragma unroll
    for (int it = 0; it < 8; it++) {
        int flat = (vb + it*256)*4;
        #pragma unroll
        for (int qq = 0; qq < 4; qq++) {
            float v = (qq==0)?f[it].x:(qq==1)?f[it].y:(qq==2)?f[it].z:f[it].w;
            int fl = flat + qq;
            int i = fl >> 7, j = fl & 127;
            bool valid = (j >= i);
            int p = i*Nn - (i*(i-1))/2 + (j - i);
            top2upd(valid ? v : -1e30f, valid ? p : 0x7fffffff, v1, j1, v2, j2);
        }
    }
    #pragma unroll
    for (int off = 16; off > 0; off >>= 1) {
        float o1 = __shfl_xor_sync(0xffffffffu, v1, off);
        int   oj1= __shfl_xor_sync(0xffffffffu, j1, off);
        float o2 = __shfl_xor_sync(0xffffffffu, v2, off);
        int   oj2= __shfl_xor_sync(0xffffffffu, j2, off);
        if (better(o1, oj1, v1, j1)) {
            if (better(v1, j1, o2, oj2)) { v2=v1; j2=j1; } else { v2=o2; j2=oj2; }
            v1=o1; j1=oj1;
        } else if (better(o1, oj1, v2, j2)) { v2=o1; j2=oj1; }
    }
    if (l == 0) { scv[w*2]=v1; sci[w*2]=j1; scv[w*2+1]=v2; sci[w*2+1]=j2; }
    __syncthreads();
    if (t == 0) {
        float b1=-1e30f, b2=-1e30f; int bi1=0x7fffffff, bi2=0x7fffffff;
        #pragma unroll
        for (int e = 0; e < 16; e++) top2upd(scv[e], sci[e], b1, bi1, b2, bi2);
        g_cv[m*16 + half*2]     = b1; g_ci[m*16 + half*2]     = bi1;
        g_cv[m*16 + half*2 + 1] = b2; g_ci[m*16 + half*2 + 1] = bi2;
    }
}

// ---------------- K2: gather + L2 norm + bf16 emit ----------------
__global__ __launch_bounds__(256) void k_norm(const float* __restrict__ vf) {
    __shared__ float tile[32*257];
    __shared__ float ssb[8][32];
    __shared__ float sinv[32];
    int b = blockIdx.y, p0 = blockIdx.x*32, t = threadIdx.x;
    int p = t & 31, c0 = t >> 5;
    int fi = g_flat[p0 + p];
    const float* base = vf + (size_t)b*Cc*NNe + fi;
    float ss = 0.f;
    #pragma unroll
    for (int k = 0; k < 32; k++) {
        int c = c0*32 + k;
        float v = base[(size_t)c*NNe];
        tile[p*257 + c] = v;
        ss += v*v;
    }
    ssb[c0][p] = ss;
    __syncthreads();
    if (t < 32) {
        float tot = 0.f;
        #pragma unroll
        for (int k = 0; k < 8; k++) tot += ssb[k][t];
        float inv = 1.0f / fmaxf(sqrtf(tot), 1e-12f);
        sinv[t] = inv;
        g_inv[b*Pn + p0 + t] = inv;
    }
    __syncthreads();
    int rowbase = b*Pn + p0;
    #pragma unroll
    for (int it = 0; it < 16; it++) {
        int id = it*256 + t;
        int pr = id >> 7, c2 = (id & 127)*2;
        float inv = sinv[pr];
        __nv_bfloat162 h = __floats2bfloat162_rn(tile[pr*257+c2]*inv, tile[pr*257+c2+1]*inv);
        *reinterpret_cast<__nv_bfloat162*>(g_vfb + (size_t)(rowbase+pr)*Cc + c2) = h;
    }
}

// ---------------- K3: merge candidates + build pos rows ----------------
__global__ __launch_bounds__(256) void k_pos(const float* __restrict__ vf) {
    __shared__ int sj;
    int r = blockIdx.x, c = threadIdx.x;
    int m = r >> 1, k = r & 1;
    if (c == 0) {
        float v1=-1e30f, v2=-1e30f; int j1=0x7fffffff, j2=0x7fffffff;
        #pragma unroll
        for (int e = 0; e < 4; e++) {   // 2 halves x 2 candidates
            float v = g_cv[m*16 + e]; int i = g_ci[m*16 + e];
            if (better(v, i, v1, j1)) { v2=v1; j2=j1; v1=v; j1=i; }
            else if (better(v, i, v2, j2)) { v2=v; j2=i; }
        }
        sj = k ? j2 : j1;
    }
    __syncthreads();
    int j = sj;
    int b = m >> 3;
    int row = b*Pn + j;
    g_posb[r*Cc + c] = g_vfb[(size_t)row*Cc + c];
    g_posf[r*Cc + c] = vf[((size_t)b*Cc + c)*NNe + g_flat[j]] * g_inv[row];
}

// ---------------- K4: persistent mma.sync GEMM + masked exp row-sum ----------------
__device__ __forceinline__ void ldm4(unsigned addr, unsigned &r0, unsigned &r1, unsigned &r2, unsigned &r3) {
    asm volatile("ldmatrix.sync.aligned.m8n8.x4.shared.b16 {%0,%1,%2,%3}, [%4];"
                 : "=r"(r0), "=r"(r1), "=r"(r2), "=r"(r3) : "r"(addr));
}
__device__ __forceinline__ void mma16816(float* c, unsigned a0, unsigned a1, unsigned a2, unsigned a3,
                                         unsigned b0, unsigned b1) {
    asm volatile("mma.sync.aligned.m16n8k16.row.col.f32.bf16.bf16.f32 "
                 "{%0,%1,%2,%3}, {%4,%5,%6,%7}, {%8,%9}, {%0,%1,%2,%3};"
                 : "+f"(c[0]), "+f"(c[1]), "+f"(c[2]), "+f"(c[3])
                 : "r"(a0), "r"(a1), "r"(a2), "r"(a3), "r"(b0), "r"(b1));
}
__device__ __forceinline__ void cp16(unsigned saddr, const void* gaddr) {
    asm volatile("cp.async.cg.shared.global [%0], [%1], 16;" :: "r"(saddr), "l"(gaddr));
}

// dynamic smem: B0 [0,32K), B1 [32K,64K), iou0 [64K,+256), iou1 [+256,+512)
constexpr int SMEM_GEMM = 65536 + 512;

__global__ __launch_bounds__(256, 2) void k_gemm() {
    extern __shared__ __align__(16) unsigned char dsm[];
    unsigned sb0 = (unsigned)__cvta_generic_to_shared(dsm);
    unsigned char* sIg = dsm + 65536;

    int t = threadIdx.x;
    int w = t >> 5, l = t & 31;

    // A fragments: loaded ONCE per persistent CTA
    int m0 = w * 16;
    int ra = m0 + (l >> 2);
    int cb = (l & 3);
    const unsigned* gA = reinterpret_cast<const unsigned*>(g_posb);
    unsigned af[16][4];
    #pragma unroll
    for (int ks = 0; ks < 16; ks++) {
        int col = ks*8 + cb;
        af[ks][0] = gA[ra*128 + col];
        af[ks][1] = gA[(ra+8)*128 + col];
        af[ks][2] = gA[ra*128 + col + 4];
        af[ks][3] = gA[(ra+8)*128 + col + 4];
    }

    // prefetch first tile
    int tile0 = blockIdx.x;
    {
        const char* gB = reinterpret_cast<const char*>(g_vfb + (size_t)tile0*64*Cc);
        #pragma unroll
        for (int it = 0; it < 8; it++) {
            int idx = it*256 + t;
            int row = idx >> 5, ch = idx & 31;
            cp16(sb0 + (row*32 + (ch ^ (row & 7)))*16, gB + row*512 + ch*16);
        }
        int b0v = (tile0*64)/Pn, j00 = tile0*64 - b0v*Pn;
        sIg[t] = g_iou[(b0v*4 + (t >> 6))*Pn + j00 + (t & 63)];
        asm volatile("cp.async.commit_group;");
    }

    int rowBbase = (l & 7) + ((l >> 4) & 1) * 8;
    int chSelB   = (l >> 3) & 1;
    const float K2E = 14.4269504088896340f;
    int mr = l >> 2;
    int nb = (l & 3) * 2;
    int rLo = m0 + mr, rHi = rLo + 8;
    int siLo = ((rLo >> 2) & 3) * 64, siHi = ((rHi >> 2) & 3) * 64;

    int cur = 0;
    for (int tile = tile0; tile < NBLK; tile += GRID) {
        int nt = tile + GRID;
        bool hn = nt < NBLK;
        if (hn) {
            const char* gB = reinterpret_cast<const char*>(g_vfb + (size_t)nt*64*Cc);
            unsigned base = sb0 + (cur ^ 1)*32768;
            #pragma unroll
            for (int it = 0; it < 8; it++) {
                int idx = it*256 + t;
                int row = idx >> 5, ch = idx & 31;
                cp16(base + (row*32 + (ch ^ (row & 7)))*16, gB + row*512 + ch*16);
            }
            int bn = (nt*64)/Pn, j0n = nt*64 - bn*Pn;
            sIg[(cur ^ 1)*256 + t] = g_iou[(bn*4 + (t >> 6))*Pn + j0n + (t & 63)];
            asm volatile("cp.async.commit_group;");
            asm volatile("cp.async.wait_group 1;");
        } else {
            asm volatile("cp.async.wait_group 0;");
        }
        __syncthreads();

        int b = (tile*64)/Pn;
        unsigned sb = sb0 + cur*32768;
        const unsigned char* sI = sIg + cur*256;

        float acc[8][4];
        #pragma unroll
        for (int i = 0; i < 8; i++)
            #pragma unroll
            for (int q = 0; q < 4; q++) acc[i][q] = 0.f;

        #pragma unroll
        for (int ks = 0; ks < 16; ks++) {
            #pragma unroll
            for (int ntp = 0; ntp < 4; ntp++) {
                int rowB = ntp*16 + rowBbase;
                int chB  = 2*ks + chSelB;
                unsigned b0, b1, b2, b3;
                ldm4(sb + rowB*512 + (((chB ^ (rowB & 7)) & 31) << 4), b0, b1, b2, b3);
                mma16816(acc[ntp*2],     af[ks][0], af[ks][1], af[ks][2], af[ks][3], b0, b1);
                mma16816(acc[ntp*2 + 1], af[ks][0], af[ks][1], af[ks][2], af[ks][3], b2, b3);
            }
        }

        bool own = (w == b);
        float sumLo = 0.f, sumHi = 0.f;
        #pragma unroll
        for (int nt2 = 0; nt2 < 8; nt2++) {
            #pragma unroll
            for (int q = 0; q < 2; q++) {
                int n = nt2*8 + nb + q;
                float eLo = fexp2(acc[nt2][q]   * K2E);
                float eHi = fexp2(acc[nt2][2+q] * K2E);
                bool mLo = own && sI[siLo + n];
                bool mHi = own && sI[siHi + n];
                sumLo += mLo ? 0.f : eLo;
                sumHi += mHi ? 0.f : eHi;
            }
        }
        sumLo += __shfl_xor_sync(0xffffffffu, sumLo, 1);
        sumLo += __shfl_xor_sync(0xffffffffu, sumLo, 2);
        sumHi += __shfl_xor_sync(0xffffffffu, sumHi, 1);
        sumHi += __shfl_xor_sync(0xffffffffu, sumHi, 2);
        if ((l & 3) == 0) {
            g_partial[rLo*NBLK + tile] = sumLo;
            g_partial[rHi*NBLK + tile] = sumHi;
        }
        __syncthreads();
        cur ^= 1;
    }
}

// ---------------- K5: negsum reduce + per-sentence pair terms (fused) ----------------
__global__ __launch_bounds__(128) void k_pairs() {
    __shared__ float sp[4*256];
    __shared__ float sneg[4];
    __shared__ float terms[16];
    int s = blockIdx.x, t = threadIdx.x;
    int w = t >> 5, l = t & 31;

    for (int i = t; i < 1024; i += 128) sp[i] = g_posf[s*1024 + i];

    // warp w reduces partials of row s*4+w (fixed order -> deterministic)
    {
        const float* prow = g_partial + (size_t)(s*4 + w)*NBLK;
        float acc = 0.f;
        for (int k = l; k < NBLK; k += 32) acc += prow[k];
        #pragma unroll
        for (int off = 16; off > 0; off >>= 1) acc += __shfl_xor_sync(0xffffffffu, acc, off);
        if (l == 0) sneg[w] = acc;
    }
    __syncthreads();

    int pair = t >> 3, cc = t & 7;
    int a_ref = pair >> 2, a_pos = pair & 3;
    float d = 0.f;
    #pragma unroll
    for (int k = 0; k < 32; k++) {
        int c = cc*32 + k;
        d += sp[a_ref*256 + c] * sp[a_pos*256 + c];
    }
    d += __shfl_xor_sync(0xffffffffu, d, 1);
    d += __shfl_xor_sync(0xffffffffu, d, 2);
    d += __shfl_xor_sync(0xffffffffu, d, 4);
    if (cc == 0) {
        float x = d * 10.0f;
        float ns = sneg[a_ref];
        terms[pair] = -(x - logf(expf(x) + ns));
    }
    __syncthreads();
    if (t == 0) {
        float su = 0.f;
        #pragma unroll
        for (int i = 0; i < 16; i++) su += terms[i];
        g_ploss[s] = su;
    }
}

// ---------------- K6: final mean ----------------
__global__ void k_final(float* out) {
    if (threadIdx.x == 0) {
        float su = 0.f;
        #pragma unroll
        for (int i = 0; i < Sv; i++) su += g_ploss[i];
        out[0] = su * (1.0f / 512.0f);
    }
}

// ---------------- launch ----------------
extern "C" void kernel_launch(void* const* d_in, const int* in_sizes, int n_in,
                              void* d_out, int out_size) {
    const float* video  = (const float*)d_in[0];
    const float* iou2d  = (const float*)d_in[4];
    const float* iou2ds = (const float*)d_in[5];
    float* out = (float*)d_out;

    cudaFuncSetAttribute(k_gemm, cudaFuncAttributeMaxDynamicSharedMemorySize, SMEM_GEMM);

    k_pre<<<2240, 256>>>(iou2d, iou2ds);
    k_norm<<<dim3(Pn/32, Bv), 256>>>(video);
    k_pos<<<RT, 256>>>(video);
    k_gemm<<<GRID, 256, SMEM_GEMM>>>();     // 4th launch -> gets profiled
    k_pairs<<<Sv, 128>>>();
    k_final<<<1, 32>>>(out);
}

// round 11
// speedup vs baseline: 1.7664x; 1.0177x over previous
#include <cuda_runtime.h>
#include <cuda_bf16.h>
#include <math.h>

// ---------------- problem constants ----------------
constexpr int Bv   = 8;      // videos
constexpr int Cc   = 256;    // feature dim
constexpr int Nn   = 128;    // N
constexpr int NNe  = Nn*Nn;  // 16384
constexpr int Sv   = 32;     // sentences
constexpr int Mv   = 64;     // moments
constexpr int Pn   = 8256;   // N*(N+1)/2 proposals
constexpr int BP   = Bv*Pn;  // 66048
constexpr int RT   = 128;    // pos rows = M*K
constexpr int NT2  = BP/32;  // 2064 GEMM column tiles (32 | Pn)
constexpr int GRID = 296;    // persistent GEMM CTAs (2 per SM x 148)

// ---------------- scratch ----------------
__device__ __align__(16) int            g_flat[Pn];
__device__ __align__(16) float          g_inv[BP];
__device__ __align__(16) __nv_bfloat16  g_vfb[(size_t)BP*Cc];
__device__ __align__(16) unsigned char  g_iou[Sv*Pn];
__device__ __align__(16) float          g_cv[Mv*16];
__device__ __align__(16) int            g_ci[Mv*16];
__device__ __align__(16) __nv_bfloat16  g_posb[RT*Cc];
__device__ __align__(16) float          g_posf[RT*Cc];
__device__ __align__(16) float          g_partial[(size_t)RT*NT2];   // [row][tile]
__device__ __align__(16) float          g_ploss[Sv];

// ---------------- fast exp2 on FMA pipe ----------------
__device__ __forceinline__ float fexp2(float x) {
    float z = __fadd_rn(x, 12582912.0f);
    float f = __fsub_rn(x, __fsub_rn(z, 12582912.0f));
    int   e = __float_as_int(z) << 23;
    float p = 1.3333558146e-3f;
    p = __fmaf_rn(p, f, 9.6181291918e-3f);
    p = __fmaf_rn(p, f, 5.5504108664e-2f);
    p = __fmaf_rn(p, f, 2.4022650696e-1f);
    p = __fmaf_rn(p, f, 6.9314718056e-1f);
    p = __fmaf_rn(p, f, 1.0f);
    return __int_as_float(__float_as_int(p) + e);
}

// ---------------- top-2 helpers (jax.lax.top_k tie semantics) ----------------
__device__ __forceinline__ bool better(float v, int i, float vx, int ix) {
    return v > vx || (v == vx && i < ix);
}
__device__ __forceinline__ void top2upd(float v, int pidx, float& v1, int& j1, float& v2, int& j2) {
    if (better(v, pidx, v1, j1)) { v2=v1; j2=j1; v1=v; j1=pidx; }
    else if (better(v, pidx, v2, j2)) { v2=v; j2=pidx; }
}

// ---------------- K1 (fused pre): flat table + iou bits + per-half top-2 ----------------
__global__ __launch_bounds__(256) void k_pre(const float* __restrict__ iou2d,
                                             const float* __restrict__ iou2ds) {
    __shared__ float scv[16];
    __shared__ int   sci[16];
    int bid = blockIdx.x, t = threadIdx.x;

    if (bid < 64) {
        int idx = bid*256 + t;
        int i = idx >> 7, j = idx & 127;
        if (j >= i) g_flat[i*Nn - (i*(i-1))/2 + (j - i)] = idx;
        return;
    }
    if (bid < 64 + 2048) {
        int r = bid - 64;
        int s = r >> 6;
        int idx = (r & 63)*256 + t;
        int i = idx >> 7, j = idx & 127;
        if (j >= i) {
            int p = i*Nn - (i*(i-1))/2 + (j - i);
            g_iou[s*Pn + p] = (iou2d[(size_t)s*NNe + idx] > 0.5f) ? 1 : 0;
        }
        return;
    }
    int r = bid - 2112;
    int m = r >> 1, half = r & 1;
    int w = t >> 5, l = t & 31;
    const float4* row = reinterpret_cast<const float4*>(iou2ds + (size_t)m*NNe);

    float4 f[8];
    int vb = half*2048 + t;
    #pragma unroll
    for (int it = 0; it < 8; it++) f[it] = row[vb + it*256];

    float v1 = -1e30f, v2 = -1e30f; int j1 = 0x7fffffff, j2 = 0x7fffffff;
    #pragma unroll
    for (int it = 0; it < 8; it++) {
        int flat = (vb + it*256)*4;
        #pragma unroll
        for (int qq = 0; qq < 4; qq++) {
            float v = (qq==0)?f[it].x:(qq==1)?f[it].y:(qq==2)?f[it].z:f[it].w;
            int fl = flat + qq;
            int i = fl >> 7, j = fl & 127;
            bool valid = (j >= i);
            int p = i*Nn - (i*(i-1))/2 + (j - i);
            top2upd(valid ? v : -1e30f, valid ? p : 0x7fffffff, v1, j1, v2, j2);
        }
    }
    #pragma unroll
    for (int off = 16; off > 0; off >>= 1) {
        float o1 = __shfl_xor_sync(0xffffffffu, v1, off);
        int   oj1= __shfl_xor_sync(0xffffffffu, j1, off);
        float o2 = __shfl_xor_sync(0xffffffffu, v2, off);
        int   oj2= __shfl_xor_sync(0xffffffffu, j2, off);
        if (better(o1, oj1, v1, j1)) {
            if (better(v1, j1, o2, oj2)) { v2=v1; j2=j1; } else { v2=o2; j2=oj2; }
            v1=o1; j1=oj1;
        } else if (better(o1, oj1, v2, j2)) { v2=o1; j2=oj1; }
    }
    if (l == 0) { scv[w*2]=v1; sci[w*2]=j1; scv[w*2+1]=v2; sci[w*2+1]=j2; }
    __syncthreads();
    if (t == 0) {
        float b1=-1e30f, b2=-1e30f; int bi1=0x7fffffff, bi2=0x7fffffff;
        #pragma unroll
        for (int e = 0; e < 16; e++) top2upd(scv[e], sci[e], b1, bi1, b2, bi2);
        g_cv[m*16 + half*2]     = b1; g_ci[m*16 + half*2]     = bi1;
        g_cv[m*16 + half*2 + 1] = b2; g_ci[m*16 + half*2 + 1] = bi2;
    }
}

// ---------------- K2: gather + L2 norm + bf16 emit ----------------
__global__ __launch_bounds__(256) void k_norm(const float* __restrict__ vf) {
    __shared__ float tile[32*257];
    __shared__ float ssb[8][32];
    __shared__ float sinv[32];
    int b = blockIdx.y, p0 = blockIdx.x*32, t = threadIdx.x;
    int p = t & 31, c0 = t >> 5;
    int fi = g_flat[p0 + p];
    const float* base = vf + (size_t)b*Cc*NNe + fi;
    float ss = 0.f;
    #pragma unroll
    for (int k = 0; k < 32; k++) {
        int c = c0*32 + k;
        float v = base[(size_t)c*NNe];
        tile[p*257 + c] = v;
        ss += v*v;
    }
    ssb[c0][p] = ss;
    __syncthreads();
    if (t < 32) {
        float tot = 0.f;
        #pragma unroll
        for (int k = 0; k < 8; k++) tot += ssb[k][t];
        float inv = 1.0f / fmaxf(sqrtf(tot), 1e-12f);
        sinv[t] = inv;
        g_inv[b*Pn + p0 + t] = inv;
    }
    __syncthreads();
    int rowbase = b*Pn + p0;
    #pragma unroll
    for (int it = 0; it < 16; it++) {
        int id = it*256 + t;
        int pr = id >> 7, c2 = (id & 127)*2;
        float inv = sinv[pr];
        __nv_bfloat162 h = __floats2bfloat162_rn(tile[pr*257+c2]*inv, tile[pr*257+c2+1]*inv);
        *reinterpret_cast<__nv_bfloat162*>(g_vfb + (size_t)(rowbase+pr)*Cc + c2) = h;
    }
}

// ---------------- K3: merge candidates + build pos rows ----------------
__global__ __launch_bounds__(256) void k_pos(const float* __restrict__ vf) {
    __shared__ int sj;
    int r = blockIdx.x, c = threadIdx.x;
    int m = r >> 1, k = r & 1;
    if (c == 0) {
        float v1=-1e30f, v2=-1e30f; int j1=0x7fffffff, j2=0x7fffffff;
        #pragma unroll
        for (int e = 0; e < 4; e++) {
            float v = g_cv[m*16 + e]; int i = g_ci[m*16 + e];
            if (better(v, i, v1, j1)) { v2=v1; j2=j1; v1=v; j1=i; }
            else if (better(v, i, v2, j2)) { v2=v; j2=i; }
        }
        sj = k ? j2 : j1;
    }
    __syncthreads();
    int j = sj;
    int b = m >> 3;
    int row = b*Pn + j;
    g_posb[r*Cc + c] = g_vfb[(size_t)row*Cc + c];
    g_posf[r*Cc + c] = vf[((size_t)b*Cc + c)*NNe + g_flat[j]] * g_inv[row];
}

// ---------------- K4: persistent mma.sync GEMM + masked exp row-sum ----------------
// 4 warps x 32 M-rows: each B fragment feeds 4 mma (2x less LDSM per MMA).
// N=32 tiles: 2064 tiles / 296 CTAs -> ~7 each, 0.4% tail imbalance.
__device__ __forceinline__ void ldm4(unsigned addr, unsigned &r0, unsigned &r1, unsigned &r2, unsigned &r3) {
    asm volatile("ldmatrix.sync.aligned.m8n8.x4.shared.b16 {%0,%1,%2,%3}, [%4];"
                 : "=r"(r0), "=r"(r1), "=r"(r2), "=r"(r3) : "r"(addr));
}
__device__ __forceinline__ void mma16816(float* c, unsigned a0, unsigned a1, unsigned a2, unsigned a3,
                                         unsigned b0, unsigned b1) {
    asm volatile("mma.sync.aligned.m16n8k16.row.col.f32.bf16.bf16.f32 "
                 "{%0,%1,%2,%3}, {%4,%5,%6,%7}, {%8,%9}, {%0,%1,%2,%3};"
                 : "+f"(c[0]), "+f"(c[1]), "+f"(c[2]), "+f"(c[3])
                 : "r"(a0), "r"(a1), "r"(a2), "r"(a3), "r"(b0), "r"(b1));
}
__device__ __forceinline__ void cp16(unsigned saddr, const void* gaddr) {
    asm volatile("cp.async.cg.shared.global [%0], [%1], 16;" :: "r"(saddr), "l"(gaddr));
}

__global__ __launch_bounds__(128, 2) void k_gemm() {
    __shared__ __align__(16) __nv_bfloat16 sB[2][32*256];   // 2 x 16KB
    __shared__ unsigned char sI[2][128];                     // 4 sent x 32 cols

    int t = threadIdx.x;
    int w = t >> 5, l = t & 31;
    unsigned sb0 = (unsigned)__cvta_generic_to_shared(&sB[0][0]);

    // A fragments once per persistent CTA: warp w owns M rows [w*32, w*32+32)
    const unsigned* gA = reinterpret_cast<const unsigned*>(g_posb);
    int cb = l & 3;
    unsigned af[16][2][4];
    #pragma unroll
    for (int ks = 0; ks < 16; ks++) {
        #pragma unroll
        for (int mt = 0; mt < 2; mt++) {
            int ra = w*32 + mt*16 + (l >> 2);
            int col = ks*8 + cb;
            af[ks][mt][0] = gA[ra*128 + col];
            af[ks][mt][1] = gA[(ra+8)*128 + col];
            af[ks][mt][2] = gA[ra*128 + col + 4];
            af[ks][mt][3] = gA[(ra+8)*128 + col + 4];
        }
    }

    // prefetch first tile
    int tile0 = blockIdx.x;
    {
        const char* gB = reinterpret_cast<const char*>(g_vfb + (size_t)tile0*32*Cc);
        #pragma unroll
        for (int it = 0; it < 8; it++) {
            int idx = it*128 + t;
            int row = idx >> 5, ch = idx & 31;
            cp16(sb0 + (row*32 + (ch ^ (row & 7)))*16, gB + row*512 + ch*16);
        }
        int b0v = (tile0*32)/Pn, j00 = tile0*32 - b0v*Pn;
        sI[0][t] = g_iou[(b0v*4 + (t >> 5))*Pn + j00 + (t & 31)];
        asm volatile("cp.async.commit_group;");
    }

    int rowBbase = (l & 7) + ((l >> 4) & 1) * 8;
    int chSelB   = (l >> 3) & 1;
    const float K2E = 14.4269504088896340f;
    int mr = l >> 2;
    int nb = (l & 3) * 2;

    int cur = 0;
    for (int tile = tile0; tile < NT2; tile += GRID) {
        int nt = tile + GRID;
        bool hn = nt < NT2;
        if (hn) {
            const char* gB = reinterpret_cast<const char*>(g_vfb + (size_t)nt*32*Cc);
            unsigned base = sb0 + (cur ^ 1)*16384;
            #pragma unroll
            for (int it = 0; it < 8; it++) {
                int idx = it*128 + t;
                int row = idx >> 5, ch = idx & 31;
                cp16(base + (row*32 + (ch ^ (row & 7)))*16, gB + row*512 + ch*16);
            }
            int bn = (nt*32)/Pn, j0n = nt*32 - bn*Pn;
            sI[cur ^ 1][t] = g_iou[(bn*4 + (t >> 5))*Pn + j0n + (t & 31)];
            asm volatile("cp.async.commit_group;");
            asm volatile("cp.async.wait_group 1;");
        } else {
            asm volatile("cp.async.wait_group 0;");
        }
        __syncthreads();

        int b = (tile*32)/Pn;
        unsigned sb = sb0 + cur*16384;
        const unsigned char* sIc = sI[cur];

        float acc[2][4][4];
        #pragma unroll
        for (int mt = 0; mt < 2; mt++)
            #pragma unroll
            for (int i = 0; i < 4; i++)
                #pragma unroll
                for (int q = 0; q < 4; q++) acc[mt][i][q] = 0.f;

        #pragma unroll
        for (int ks = 0; ks < 16; ks++) {
            #pragma unroll
            for (int ntp = 0; ntp < 2; ntp++) {
                int rowB = ntp*16 + rowBbase;
                int chB  = 2*ks + chSelB;
                unsigned b0, b1, b2, b3;
                ldm4(sb + rowB*512 + (((chB ^ (rowB & 7)) & 31) << 4), b0, b1, b2, b3);
                #pragma unroll
                for (int mt = 0; mt < 2; mt++) {
                    mma16816(acc[mt][ntp*2],     af[ks][mt][0], af[ks][mt][1], af[ks][mt][2], af[ks][mt][3], b0, b1);
                    mma16816(acc[mt][ntp*2 + 1], af[ks][mt][0], af[ks][mt][1], af[ks][mt][2], af[ks][mt][3], b2, b3);
                }
            }
        }

        // epilogue: exp((dot)/T) with neg mask, per-row partial sums
        #pragma unroll
        for (int mt = 0; mt < 2; mt++) {
            int rLo = w*32 + mt*16 + mr, rHi = rLo + 8;
            bool own = ((2*w + mt) == b);
            int siLo = ((rLo >> 2) & 3) * 32, siHi = ((rHi >> 2) & 3) * 32;
            float sumLo = 0.f, sumHi = 0.f;
            #pragma unroll
            for (int nt2 = 0; nt2 < 4; nt2++) {
                #pragma unroll
                for (int q = 0; q < 2; q++) {
                    int n = nt2*8 + nb + q;
                    float eLo = fexp2(acc[mt][nt2][q]   * K2E);
                    float eHi = fexp2(acc[mt][nt2][2+q] * K2E);
                    bool mLo = own && sIc[siLo + n];
                    bool mHi = own && sIc[siHi + n];
                    sumLo += mLo ? 0.f : eLo;
                    sumHi += mHi ? 0.f : eHi;
                }
            }
            sumLo += __shfl_xor_sync(0xffffffffu, sumLo, 1);
            sumLo += __shfl_xor_sync(0xffffffffu, sumLo, 2);
            sumHi += __shfl_xor_sync(0xffffffffu, sumHi, 1);
            sumHi += __shfl_xor_sync(0xffffffffu, sumHi, 2);
            if ((l & 3) == 0) {
                g_partial[(size_t)rLo*NT2 + tile] = sumLo;
                g_partial[(size_t)rHi*NT2 + tile] = sumHi;
            }
        }
        __syncthreads();
        cur ^= 1;
    }
}

// ---------------- K5: negsum reduce + per-sentence pair terms (fused) ----------------
__global__ __launch_bounds__(128) void k_pairs() {
    __shared__ float sp[4*256];
    __shared__ float sneg[4];
    __shared__ float terms[16];
    int s = blockIdx.x, t = threadIdx.x;
    int w = t >> 5, l = t & 31;

    for (int i = t; i < 1024; i += 128) sp[i] = g_posf[s*1024 + i];

    {
        const float* prow = g_partial + (size_t)(s*4 + w)*NT2;
        float acc = 0.f;
        for (int k = l; k < NT2; k += 32) acc += prow[k];
        #pragma unroll
        for (int off = 16; off > 0; off >>= 1) acc += __shfl_xor_sync(0xffffffffu, acc, off);
        if (l == 0) sneg[w] = acc;
    }
    __syncthreads();

    int pair = t >> 3, cc = t & 7;
    int a_ref = pair >> 2, a_pos = pair & 3;
    float d = 0.f;
    #pragma unroll
    for (int k = 0; k < 32; k++) {
        int c = cc*32 + k;
        d += sp[a_ref*256 + c] * sp[a_pos*256 + c];
    }
    d += __shfl_xor_sync(0xffffffffu, d, 1);
    d += __shfl_xor_sync(0xffffffffu, d, 2);
    d += __shfl_xor_sync(0xffffffffu, d, 4);
    if (cc == 0) {
        float x = d * 10.0f;
        float ns = sneg[a_ref];
        terms[pair] = -(x - logf(expf(x) + ns));
    }
    __syncthreads();
    if (t == 0) {
        float su = 0.f;
        #pragma unroll
        for (int i = 0; i < 16; i++) su += terms[i];
        g_ploss[s] = su;
    }
}

// ---------------- K6: final mean ----------------
__global__ void k_final(float* out) {
    if (threadIdx.x == 0) {
        float su = 0.f;
        #pragma unroll
        for (int i = 0; i < Sv; i++) su += g_ploss[i];
        out[0] = su * (1.0f / 512.0f);
    }
}

// ---------------- launch ----------------
extern "C" void kernel_launch(void* const* d_in, const int* in_sizes, int n_in,
                              void* d_out, int out_size) {
    const float* video  = (const float*)d_in[0];
    const float* iou2d  = (const float*)d_in[4];
    const float* iou2ds = (const float*)d_in[5];
    float* out = (float*)d_out;

    k_pre<<<2240, 256>>>(iou2d, iou2ds);
    k_norm<<<dim3(Pn/32, Bv), 256>>>(video);
    k_pos<<<RT, 256>>>(video);
    k_gemm<<<GRID, 128>>>();     // 4th launch -> profiled
    k_pairs<<<Sv, 128>>>();
    k_final<<<1, 32>>>(out);
}